// round 3
// baseline (speedup 1.0000x reference)
#include <cuda_runtime.h>
#include <math.h>

#define DIM   768
#define NH    12
#define HD    64
#define HID   3072
#define BATCH 4
#define SEQ   2048
#define NT    (BATCH*SEQ)   /* 8192 tokens */
#define NBH   (BATCH*NH)    /* 48 (b,h) pairs */
#define ATTN_SCALE 0.125f   /* 64^-0.5 */

/* ---------------- scratch (device globals; no allocs allowed) ------------- */
__device__ float g_h   [(size_t)NT * DIM];        /* LN1 out            */
__device__ float g_qkv [(size_t)NT * 3 * DIM];    /* qkv                */
__device__ float g_sc  [(size_t)NBH * SEQ * SEQ]; /* attention scores   */
__device__ float g_attn[(size_t)NT * DIM];        /* attn output        */
__device__ float g_x1  [(size_t)NT * DIM];        /* x + proj           */
__device__ float g_h2  [(size_t)NT * DIM];        /* LN2 out            */
__device__ float g_act [(size_t)NT * HID];        /* gelu(ffn1)         */

/* ---------------- layernorm ---------------------------------------------- */
__global__ __launch_bounds__(256) void ln_kernel(
    const float* __restrict__ x, const float* __restrict__ gamma,
    const float* __restrict__ beta, float* __restrict__ out)
{
    int row = blockIdx.x;
    const float* xr = x + (size_t)row * DIM;
    float s = 0.f, s2 = 0.f;
    for (int i = threadIdx.x; i < DIM; i += 256) {
        float v = xr[i]; s += v; s2 += v * v;
    }
    __shared__ float sh[64];
    #pragma unroll
    for (int o = 16; o > 0; o >>= 1) {
        s  += __shfl_xor_sync(0xffffffffu, s,  o);
        s2 += __shfl_xor_sync(0xffffffffu, s2, o);
    }
    int warp = threadIdx.x >> 5, lane = threadIdx.x & 31;
    if (lane == 0) { sh[warp] = s; sh[warp + 32] = s2; }
    __syncthreads();
    if (threadIdx.x < 32) {
        s  = (threadIdx.x < 8) ? sh[threadIdx.x]      : 0.f;
        s2 = (threadIdx.x < 8) ? sh[threadIdx.x + 32] : 0.f;
        #pragma unroll
        for (int o = 4; o > 0; o >>= 1) {
            s  += __shfl_xor_sync(0xffffffffu, s,  o);
            s2 += __shfl_xor_sync(0xffffffffu, s2, o);
        }
        if (lane == 0) { sh[0] = s; sh[1] = s2; }
    }
    __syncthreads();
    float mu  = sh[0] * (1.f / DIM);
    float var = sh[1] * (1.f / DIM) - mu * mu;
    float inv = rsqrtf(var + 1e-6f);
    float* orow = out + (size_t)row * DIM;
    for (int i = threadIdx.x; i < DIM; i += 256)
        orow[i] = (xr[i] - mu) * inv * gamma[i] + beta[i];
}

/* ---------------- softmax over rows of 2048 ------------------------------ */
__global__ __launch_bounds__(256) void softmax_kernel(float* __restrict__ scores)
{
    float* p = scores + (size_t)blockIdx.x * SEQ;
    float v[8];
    float mx = -1e30f;
    #pragma unroll
    for (int j = 0; j < 8; j++) {
        v[j] = p[threadIdx.x + 256 * j];
        mx = fmaxf(mx, v[j]);
    }
    __shared__ float sh[8];
    #pragma unroll
    for (int o = 16; o > 0; o >>= 1) mx = fmaxf(mx, __shfl_xor_sync(0xffffffffu, mx, o));
    int warp = threadIdx.x >> 5, lane = threadIdx.x & 31;
    if (lane == 0) sh[warp] = mx;
    __syncthreads();
    mx = fmaxf(fmaxf(fmaxf(sh[0], sh[1]), fmaxf(sh[2], sh[3])),
               fmaxf(fmaxf(sh[4], sh[5]), fmaxf(sh[6], sh[7])));
    float sum = 0.f;
    #pragma unroll
    for (int j = 0; j < 8; j++) { v[j] = __expf(v[j] - mx); sum += v[j]; }
    #pragma unroll
    for (int o = 16; o > 0; o >>= 1) sum += __shfl_xor_sync(0xffffffffu, sum, o);
    __syncthreads();
    if (lane == 0) sh[warp] = sum;
    __syncthreads();
    sum = sh[0] + sh[1] + sh[2] + sh[3] + sh[4] + sh[5] + sh[6] + sh[7];
    float inv = 1.f / sum;
    #pragma unroll
    for (int j = 0; j < 8; j++) p[threadIdx.x + 256 * j] = v[j] * inv;
}

/* ---------------- generic tiled SGEMM (NN), fused epilogue ---------------- */
/* C[M,N] = A[M,K] @ B[K,N] (+bias) (gelu) (+resid). 64x64 tile, BK=16,
   256 threads, 4x4 register micro-tile. M,N % 64 == 0, K % 16 == 0. */
template<bool BIAS, bool RESID, bool GELU>
__global__ __launch_bounds__(256) void gemm_nn(
    const float* __restrict__ A, int lda,
    const float* __restrict__ B, int ldb,
    const float* __restrict__ bias,
    const float* __restrict__ resid, int ldr,
    float* __restrict__ C, int ldc,
    int M, int N, int K)
{
    __shared__ __align__(16) float As[16][64];
    __shared__ __align__(16) float Bs[16][64];
    const int tid = threadIdx.x;
    const int tx = tid & 15, ty = tid >> 4;
    const int m0 = blockIdx.y * 64, n0 = blockIdx.x * 64;
    const int arow = tid >> 2, akc = (tid & 3) << 2;
    const int brow = tid >> 4, bnc = (tid & 15) << 2;
    const float* aptr = A + (size_t)(m0 + arow) * lda + akc;
    const float* bptr = B + (size_t)brow * ldb + n0 + bnc;
    float acc[4][4] = {};
    for (int k0 = 0; k0 < K; k0 += 16) {
        float4 av = *(const float4*)(aptr + k0);
        float4 bv = *(const float4*)(bptr + (size_t)k0 * ldb);
        __syncthreads();
        As[akc + 0][arow] = av.x; As[akc + 1][arow] = av.y;
        As[akc + 2][arow] = av.z; As[akc + 3][arow] = av.w;
        *(float4*)&Bs[brow][bnc] = bv;
        __syncthreads();
        #pragma unroll
        for (int k = 0; k < 16; k++) {
            float4 a = *(const float4*)&As[k][ty << 2];
            float4 b = *(const float4*)&Bs[k][tx << 2];
            acc[0][0] += a.x*b.x; acc[0][1] += a.x*b.y; acc[0][2] += a.x*b.z; acc[0][3] += a.x*b.w;
            acc[1][0] += a.y*b.x; acc[1][1] += a.y*b.y; acc[1][2] += a.y*b.z; acc[1][3] += a.y*b.w;
            acc[2][0] += a.z*b.x; acc[2][1] += a.z*b.y; acc[2][2] += a.z*b.z; acc[2][3] += a.z*b.w;
            acc[3][0] += a.w*b.x; acc[3][1] += a.w*b.y; acc[3][2] += a.w*b.z; acc[3][3] += a.w*b.w;
        }
    }
    #pragma unroll
    for (int i = 0; i < 4; i++) {
        int m = m0 + (ty << 2) + i;
        #pragma unroll
        for (int j = 0; j < 4; j++) {
            int n = n0 + (tx << 2) + j;
            float v = acc[i][j];
            if (BIAS)  v += bias[n];
            if (GELU)  v = 0.5f * v * (1.f + erff(v * 0.7071067811865476f));
            if (RESID) v += resid[(size_t)m * ldr + n];
            C[(size_t)m * ldc + n] = v;
        }
    }
}

/* ---------------- scores = scale * Q K^T, masked (batched NT GEMM) -------- */
__global__ __launch_bounds__(256) void attn_scores_kernel(
    const float* __restrict__ qkv, const int* __restrict__ mask,
    float* __restrict__ scores)
{
    const int z = blockIdx.z, b = z / NH, h = z % NH;
    const float* Aq = qkv + (size_t)b * SEQ * (3 * DIM) + h * HD;        /* Q */
    const float* Bk = qkv + (size_t)b * SEQ * (3 * DIM) + DIM + h * HD;  /* K */
    const int*   mb = mask + (size_t)b * SEQ * SEQ;
    float*       C  = scores + (size_t)z * SEQ * SEQ;

    __shared__ __align__(16) float As[16][64];
    __shared__ __align__(16) float Bs[16][64];
    const int tid = threadIdx.x;
    const int tx = tid & 15, ty = tid >> 4;
    const int m0 = blockIdx.y * 64, n0 = blockIdx.x * 64;
    const int row = tid >> 2, kc = (tid & 3) << 2;
    float acc[4][4] = {};
    #pragma unroll
    for (int k0 = 0; k0 < HD; k0 += 16) {
        float4 av = *(const float4*)(Aq + (size_t)(m0 + row) * (3 * DIM) + k0 + kc);
        float4 bv = *(const float4*)(Bk + (size_t)(n0 + row) * (3 * DIM) + k0 + kc);
        __syncthreads();
        As[kc + 0][row] = av.x; As[kc + 1][row] = av.y; As[kc + 2][row] = av.z; As[kc + 3][row] = av.w;
        Bs[kc + 0][row] = bv.x; Bs[kc + 1][row] = bv.y; Bs[kc + 2][row] = bv.z; Bs[kc + 3][row] = bv.w;
        __syncthreads();
        #pragma unroll
        for (int k = 0; k < 16; k++) {
            float4 a = *(const float4*)&As[k][ty << 2];
            float4 b2 = *(const float4*)&Bs[k][tx << 2];
            acc[0][0] += a.x*b2.x; acc[0][1] += a.x*b2.y; acc[0][2] += a.x*b2.z; acc[0][3] += a.x*b2.w;
            acc[1][0] += a.y*b2.x; acc[1][1] += a.y*b2.y; acc[1][2] += a.y*b2.z; acc[1][3] += a.y*b2.w;
            acc[2][0] += a.z*b2.x; acc[2][1] += a.z*b2.y; acc[2][2] += a.z*b2.z; acc[2][3] += a.z*b2.w;
            acc[3][0] += a.w*b2.x; acc[3][1] += a.w*b2.y; acc[3][2] += a.w*b2.z; acc[3][3] += a.w*b2.w;
        }
    }
    #pragma unroll
    for (int i = 0; i < 4; i++) {
        int m = m0 + (ty << 2) + i;
        #pragma unroll
        for (int j = 0; j < 4; j++) {
            int n = n0 + (tx << 2) + j;
            int mv = mb[(size_t)m * SEQ + n];
            C[(size_t)m * SEQ + n] = mv ? acc[i][j] * ATTN_SCALE : -10000.f;
        }
    }
}

/* ---------------- attn_out = P @ V (batched NN GEMM, N=64) ---------------- */
__global__ __launch_bounds__(256) void attn_av_kernel(
    const float* __restrict__ scores, const float* __restrict__ qkv,
    float* __restrict__ attn)
{
    const int z = blockIdx.z, b = z / NH, h = z % NH;
    const float* A = scores + (size_t)z * SEQ * SEQ;                         /* lda SEQ   */
    const float* B = qkv + (size_t)b * SEQ * (3 * DIM) + 2 * DIM + h * HD;   /* ldb 2304  */
    float*       C = attn + (size_t)b * SEQ * DIM + h * HD;                  /* ldc 768   */

    __shared__ __align__(16) float As[16][64];
    __shared__ __align__(16) float Bs[16][64];
    const int tid = threadIdx.x;
    const int tx = tid & 15, ty = tid >> 4;
    const int m0 = blockIdx.y * 64;
    const int arow = tid >> 2, akc = (tid & 3) << 2;
    const int brow = tid >> 4, bnc = (tid & 15) << 2;
    float acc[4][4] = {};
    for (int k0 = 0; k0 < SEQ; k0 += 16) {
        float4 av = *(const float4*)(A + (size_t)(m0 + arow) * SEQ + k0 + akc);
        float4 bv = *(const float4*)(B + (size_t)(k0 + brow) * (3 * DIM) + bnc);
        __syncthreads();
        As[akc + 0][arow] = av.x; As[akc + 1][arow] = av.y;
        As[akc + 2][arow] = av.z; As[akc + 3][arow] = av.w;
        *(float4*)&Bs[brow][bnc] = bv;
        __syncthreads();
        #pragma unroll
        for (int k = 0; k < 16; k++) {
            float4 a = *(const float4*)&As[k][ty << 2];
            float4 b2 = *(const float4*)&Bs[k][tx << 2];
            acc[0][0] += a.x*b2.x; acc[0][1] += a.x*b2.y; acc[0][2] += a.x*b2.z; acc[0][3] += a.x*b2.w;
            acc[1][0] += a.y*b2.x; acc[1][1] += a.y*b2.y; acc[1][2] += a.y*b2.z; acc[1][3] += a.y*b2.w;
            acc[2][0] += a.z*b2.x; acc[2][1] += a.z*b2.y; acc[2][2] += a.z*b2.z; acc[2][3] += a.z*b2.w;
            acc[3][0] += a.w*b2.x; acc[3][1] += a.w*b2.y; acc[3][2] += a.w*b2.z; acc[3][3] += a.w*b2.w;
        }
    }
    #pragma unroll
    for (int i = 0; i < 4; i++) {
        int m = m0 + (ty << 2) + i;
        #pragma unroll
        for (int j = 0; j < 4; j++) {
            int n = (tx << 2) + j;
            C[(size_t)m * DIM + n] = acc[i][j];
        }
    }
}

/* ---------------- driver --------------------------------------------------- */
extern "C" void kernel_launch(void* const* d_in, const int* in_sizes, int n_in,
                              void* d_out, int out_size)
{
    const float* x      = (const float*)d_in[0];
    const int*   mask   = (const int*)  d_in[1];
    const float* w_qkv  = (const float*)d_in[2];
    const float* b_qkv  = (const float*)d_in[3];
    const float* w_proj = (const float*)d_in[4];
    const float* b_proj = (const float*)d_in[5];
    const float* g1     = (const float*)d_in[6];
    const float* beta1  = (const float*)d_in[7];
    const float* g2     = (const float*)d_in[8];
    const float* beta2  = (const float*)d_in[9];
    const float* w1     = (const float*)d_in[10];
    const float* b1     = (const float*)d_in[11];
    const float* w2     = (const float*)d_in[12];
    const float* b2     = (const float*)d_in[13];
    float* out = (float*)d_out;

    float *ph, *pqkv, *psc, *pattn, *px1, *ph2, *pact;
    cudaGetSymbolAddress((void**)&ph,    g_h);
    cudaGetSymbolAddress((void**)&pqkv,  g_qkv);
    cudaGetSymbolAddress((void**)&psc,   g_sc);
    cudaGetSymbolAddress((void**)&pattn, g_attn);
    cudaGetSymbolAddress((void**)&px1,   g_x1);
    cudaGetSymbolAddress((void**)&ph2,   g_h2);
    cudaGetSymbolAddress((void**)&pact,  g_act);

    /* 1. h = LN(x) */
    ln_kernel<<<NT, 256>>>(x, g1, beta1, ph);
    /* 2. qkv = h @ w_qkv + b_qkv   (8192 x 2304 x 768) */
    gemm_nn<true, false, false><<<dim3(36, 128, 1), 256>>>(
        ph, DIM, w_qkv, 3 * DIM, b_qkv, nullptr, 0, pqkv, 3 * DIM, NT, 3 * DIM, DIM);
    /* 3. scores = mask(scale * Q K^T) */
    attn_scores_kernel<<<dim3(32, 32, NBH), 256>>>(pqkv, mask, psc);
    /* 4. softmax rows */
    softmax_kernel<<<NBH * SEQ, 256>>>(psc);
    /* 5. attn = P @ V */
    attn_av_kernel<<<dim3(1, 32, NBH), 256>>>(psc, pqkv, pattn);
    /* 6. x1 = x + attn @ w_proj + b_proj */
    gemm_nn<true, true, false><<<dim3(12, 128, 1), 256>>>(
        pattn, DIM, w_proj, DIM, b_proj, x, DIM, px1, DIM, NT, DIM, DIM);
    /* 7. h2 = LN(x1) */
    ln_kernel<<<NT, 256>>>(px1, g2, beta2, ph2);
    /* 8. act = gelu(h2 @ w1 + b1)   (8192 x 3072 x 768) */
    gemm_nn<true, false, true><<<dim3(48, 128, 1), 256>>>(
        ph2, DIM, w1, HID, b1, nullptr, 0, pact, HID, NT, HID, DIM);
    /* 9. out = x1 + act @ w2 + b2   (8192 x 768 x 3072) */
    gemm_nn<true, true, false><<<dim3(12, 128, 1), 256>>>(
        pact, HID, w2, DIM, b2, px1, DIM, out, DIM, NT, DIM, HID);
}

// round 6
// speedup vs baseline: 2.1725x; 2.1725x over previous
#include <cuda_runtime.h>
#include <cuda_bf16.h>
#include <math.h>
#include <cstdint>

#define DIM   768
#define NH    12
#define HD    64
#define HID   3072
#define BATCH 4
#define SEQ   2048
#define NT    (BATCH*SEQ)
#define NBH   (BATCH*NH)
#define ATTN_SCALE 0.125f

typedef __nv_bfloat16 bf16;

/* ---------------- scratch planes (device globals) ---------------- */
__device__ unsigned short g_h_hi [(size_t)NT * DIM],      g_h_lo [(size_t)NT * DIM];
__device__ unsigned short g_qkv_hi[(size_t)NT * 3 * DIM], g_qkv_lo[(size_t)NT * 3 * DIM];
__device__ float          g_sc   [(size_t)NBH * SEQ * SEQ];
__device__ unsigned short g_P_hi [(size_t)NBH * SEQ * SEQ], g_P_lo[(size_t)NBH * SEQ * SEQ];
__device__ unsigned short g_at_hi[(size_t)NT * DIM],      g_at_lo[(size_t)NT * DIM];
__device__ float          g_x1   [(size_t)NT * DIM];
__device__ unsigned short g_h2_hi[(size_t)NT * DIM],      g_h2_lo[(size_t)NT * DIM];
__device__ unsigned short g_ac_hi[(size_t)NT * HID],      g_ac_lo[(size_t)NT * HID];
__device__ unsigned short g_wqkv_hi[768*2304], g_wqkv_lo[768*2304];
__device__ unsigned short g_wpr_hi [768*768],  g_wpr_lo [768*768];
__device__ unsigned short g_w1_hi  [768*3072], g_w1_lo  [768*3072];
__device__ unsigned short g_w2_hi  [3072*768], g_w2_lo  [3072*768];

/* ---------------- mma / ldmatrix primitives ---------------- */
__device__ __forceinline__ uint32_t smem_u32(const void* p) {
    uint32_t a;
    asm("{ .reg .u64 t; cvta.to.shared.u64 t, %1; cvt.u32.u64 %0, t; }" : "=r"(a) : "l"(p));
    return a;
}
__device__ __forceinline__ void ldsm4(uint32_t* r, uint32_t a) {
    asm volatile("ldmatrix.sync.aligned.m8n8.x4.shared.b16 {%0,%1,%2,%3}, [%4];"
                 : "=r"(r[0]),"=r"(r[1]),"=r"(r[2]),"=r"(r[3]) : "r"(a));
}
__device__ __forceinline__ void ldsm2(uint32_t* r, uint32_t a) {
    asm volatile("ldmatrix.sync.aligned.m8n8.x2.shared.b16 {%0,%1}, [%2];"
                 : "=r"(r[0]),"=r"(r[1]) : "r"(a));
}
__device__ __forceinline__ void ldsm2t(uint32_t* r, uint32_t a) {
    asm volatile("ldmatrix.sync.aligned.m8n8.x2.trans.shared.b16 {%0,%1}, [%2];"
                 : "=r"(r[0]),"=r"(r[1]) : "r"(a));
}
__device__ __forceinline__ void mma_bf16(float* d, const uint32_t* a, const uint32_t* b) {
    asm volatile("mma.sync.aligned.m16n8k16.row.col.f32.bf16.bf16.f32 "
                 "{%0,%1,%2,%3}, {%4,%5,%6,%7}, {%8,%9}, {%0,%1,%2,%3};"
                 : "+f"(d[0]),"+f"(d[1]),"+f"(d[2]),"+f"(d[3])
                 : "r"(a[0]),"r"(a[1]),"r"(a[2]),"r"(a[3]),"r"(b[0]),"r"(b[1]));
}

/* smem layouts:
   A-style tile [rows][32] bf16, 64B rows, swizzle c ^ ((r>>1)&3)  -> conflict-free ldmatrix
   B-trans tile [32][NTILE] bf16, swizzle c ^ (k&7)                -> conflict-free ldmatrix.trans */
__device__ __forceinline__ int a_off(int r, int c) { return r * 64 + ((c ^ ((r >> 1) & 3)) << 4); }
template<int NTILE>
__device__ __forceinline__ int bt_off(int k, int c) { return k * (NTILE * 2) + ((c ^ (k & 7)) << 4); }

/* global -> smem tile loaders (hi+lo planes) */
__device__ __forceinline__ void ld_atile(char* dh, char* dl,
    const bf16* gh, const bf16* gl, int stride, int tid)
{
    int row = tid >> 1, cp = (tid & 1) * 2;
    size_t o = (size_t)row * stride + cp * 8;
    uint4 h0 = *(const uint4*)(gh + o), h1 = *(const uint4*)(gh + o + 8);
    uint4 l0 = *(const uint4*)(gl + o), l1 = *(const uint4*)(gl + o + 8);
    *(uint4*)(dh + a_off(row, cp))     = h0;
    *(uint4*)(dh + a_off(row, cp + 1)) = h1;
    *(uint4*)(dl + a_off(row, cp))     = l0;
    *(uint4*)(dl + a_off(row, cp + 1)) = l1;
}
template<int NTILE>
__device__ __forceinline__ void ld_bttile(char* dh, char* dl,
    const bf16* gh, const bf16* gl, int ldb, int tid)
{
    int k = tid >> 3, cb = tid & 7;
    size_t o = (size_t)k * ldb + cb * 8;
    uint4 h0 = *(const uint4*)(gh + o);
    uint4 l0 = *(const uint4*)(gl + o);
    *(uint4*)(dh + bt_off<NTILE>(k, cb)) = h0;
    *(uint4*)(dl + bt_off<NTILE>(k, cb)) = l0;
    if (NTILE == 128) {
        uint4 h1 = *(const uint4*)(gh + o + 64);
        uint4 l1 = *(const uint4*)(gl + o + 64);
        *(uint4*)(dh + bt_off<NTILE>(k, cb + 8)) = h1;
        *(uint4*)(dl + bt_off<NTILE>(k, cb + 8)) = l1;
    }
}

/* one BK=32 chunk of split-mma: acc += Ah*Bh + Ah*Bl + Al*Bh */
template<int MT, bool BTRANS, int NTILE>
__device__ __forceinline__ void mma_chunk(
    uint32_t sAh, uint32_t sAl, uint32_t sBh, uint32_t sBl,
    int wm, int wn, int lane, float acc[][4][4])
{
    const int jA = lane >> 3, rA = lane & 7;
    const int jB = (lane >> 3) & 1, rB = lane & 7;
    #pragma unroll
    for (int ks = 0; ks < 32; ks += 16) {
        uint32_t Ah[MT][4], Al[MT][4], Bh[4][2], Bl[4][2];
        #pragma unroll
        for (int mt = 0; mt < MT; mt++) {
            int row = wm * MT * 16 + mt * 16 + (jA & 1) * 8 + rA;
            int cc  = (ks >> 3) + (jA >> 1);
            ldsm4(Ah[mt], sAh + a_off(row, cc));
            ldsm4(Al[mt], sAl + a_off(row, cc));
        }
        #pragma unroll
        for (int nt = 0; nt < 4; nt++) {
            if (BTRANS) {
                int krow = ks + jB * 8 + rB;
                int cc   = (wn * 32 + nt * 8) >> 3;
                ldsm2t(Bh[nt], sBh + bt_off<NTILE>(krow, cc));
                ldsm2t(Bl[nt], sBl + bt_off<NTILE>(krow, cc));
            } else {
                int nrow = wn * 32 + nt * 8 + rB;
                int cc   = (ks >> 3) + jB;
                ldsm2(Bh[nt], sBh + a_off(nrow, cc));
                ldsm2(Bl[nt], sBl + a_off(nrow, cc));
            }
        }
        #pragma unroll
        for (int mt = 0; mt < MT; mt++)
            #pragma unroll
            for (int nt = 0; nt < 4; nt++) {
                mma_bf16(acc[mt][nt], Ah[mt], Bh[nt]);
                mma_bf16(acc[mt][nt], Ah[mt], Bl[nt]);
                mma_bf16(acc[mt][nt], Al[mt], Bh[nt]);
            }
    }
}

__device__ __forceinline__ void store_split2(bf16* hi, bf16* lo, size_t off,
                                             float v0, float v1)
{
    bf16 h0 = __float2bfloat16(v0), h1 = __float2bfloat16(v1);
    __nv_bfloat162 H; H.x = h0; H.y = h1;
    __nv_bfloat162 L;
    L.x = __float2bfloat16(v0 - __bfloat162float(h0));
    L.y = __float2bfloat16(v1 - __bfloat162float(h1));
    *(__nv_bfloat162*)(hi + off) = H;
    *(__nv_bfloat162*)(lo + off) = L;
}

/* ================= layernorm -> split planes ================= */
__global__ __launch_bounds__(256) void ln_split(
    const float* __restrict__ x, const float* __restrict__ gamma,
    const float* __restrict__ beta, bf16* __restrict__ ohi, bf16* __restrict__ olo)
{
    int row = blockIdx.x;
    const float* xr = x + (size_t)row * DIM;
    float s = 0.f, s2 = 0.f;
    for (int i = threadIdx.x; i < DIM; i += 256) { float v = xr[i]; s += v; s2 += v * v; }
    __shared__ float sh[64];
    #pragma unroll
    for (int o = 16; o > 0; o >>= 1) {
        s  += __shfl_xor_sync(0xffffffffu, s,  o);
        s2 += __shfl_xor_sync(0xffffffffu, s2, o);
    }
    int warp = threadIdx.x >> 5, lane = threadIdx.x & 31;
    if (lane == 0) { sh[warp] = s; sh[warp + 32] = s2; }
    __syncthreads();
    if (threadIdx.x < 32) {
        s  = (threadIdx.x < 8) ? sh[threadIdx.x]      : 0.f;
        s2 = (threadIdx.x < 8) ? sh[threadIdx.x + 32] : 0.f;
        #pragma unroll
        for (int o = 4; o > 0; o >>= 1) {
            s  += __shfl_xor_sync(0xffffffffu, s,  o);
            s2 += __shfl_xor_sync(0xffffffffu, s2, o);
        }
        if (lane == 0) { sh[0] = s; sh[1] = s2; }
    }
    __syncthreads();
    float mu  = sh[0] * (1.f / DIM);
    float inv = rsqrtf(sh[1] * (1.f / DIM) - mu * mu + 1e-6f);
    for (int i = threadIdx.x; i < DIM; i += 256) {
        float v = (xr[i] - mu) * inv * gamma[i] + beta[i];
        bf16 h = __float2bfloat16(v);
        ohi[(size_t)row * DIM + i] = h;
        olo[(size_t)row * DIM + i] = __float2bfloat16(v - __bfloat162float(h));
    }
}

/* ================= weight split ================= */
__global__ __launch_bounds__(256) void wsplit(
    const float* __restrict__ src, bf16* __restrict__ hi, bf16* __restrict__ lo, int n)
{
    int i = (blockIdx.x * 256 + threadIdx.x) * 4;
    if (i >= n) return;
    float4 v = *(const float4*)(src + i);
    store_split2(hi, lo, i,     v.x, v.y);
    store_split2(hi, lo, i + 2, v.z, v.w);
}

/* ================= softmax -> split planes ================= */
__global__ __launch_bounds__(256) void softmax_split(
    const float* __restrict__ sc, bf16* __restrict__ phi, bf16* __restrict__ plo)
{
    const float* p = sc + (size_t)blockIdx.x * SEQ;
    float2 v[4];
    float mx = -1e30f;
    #pragma unroll
    for (int j = 0; j < 4; j++) {
        v[j] = *(const float2*)(p + threadIdx.x * 2 + j * 512);
        mx = fmaxf(mx, fmaxf(v[j].x, v[j].y));
    }
    __shared__ float sh[8];
    #pragma unroll
    for (int o = 16; o > 0; o >>= 1) mx = fmaxf(mx, __shfl_xor_sync(0xffffffffu, mx, o));
    int warp = threadIdx.x >> 5, lane = threadIdx.x & 31;
    if (lane == 0) sh[warp] = mx;
    __syncthreads();
    mx = fmaxf(fmaxf(fmaxf(sh[0], sh[1]), fmaxf(sh[2], sh[3])),
               fmaxf(fmaxf(sh[4], sh[5]), fmaxf(sh[6], sh[7])));
    float sum = 0.f;
    #pragma unroll
    for (int j = 0; j < 4; j++) {
        v[j].x = __expf(v[j].x - mx); v[j].y = __expf(v[j].y - mx);
        sum += v[j].x + v[j].y;
    }
    #pragma unroll
    for (int o = 16; o > 0; o >>= 1) sum += __shfl_xor_sync(0xffffffffu, sum, o);
    __syncthreads();
    if (lane == 0) sh[warp] = sum;
    __syncthreads();
    sum = sh[0] + sh[1] + sh[2] + sh[3] + sh[4] + sh[5] + sh[6] + sh[7];
    float inv = 1.f / sum;
    size_t base = (size_t)blockIdx.x * SEQ + threadIdx.x * 2;
    #pragma unroll
    for (int j = 0; j < 4; j++)
        store_split2(phi, plo, base + j * 512, v[j].x * inv, v[j].y * inv);
}

/* ================= linear GEMM: C = A@W (+bias)(gelu)(+resid) ================= */
template<bool GELU, bool RESID, bool SPLITOUT>
__global__ __launch_bounds__(256) void lin_gemm(
    const bf16* __restrict__ Ahi, const bf16* __restrict__ Alo, int lda,
    const bf16* __restrict__ Whi, const bf16* __restrict__ Wlo, int ldb,
    const float* __restrict__ bias, const float* __restrict__ resid,
    float* __restrict__ outf, bf16* __restrict__ ohi, bf16* __restrict__ olo,
    int ldc, int K)
{
    __shared__ __align__(1024) char sm[32768];
    char *Ah_ = sm, *Al_ = sm + 8192, *Bh_ = sm + 16384, *Bl_ = sm + 24576;
    uint32_t sb = smem_u32(sm);
    const int tid = threadIdx.x, lane = tid & 31, wid = tid >> 5;
    const int wm = wid >> 2, wn = wid & 3;
    const int m0 = blockIdx.y * 128, n0 = blockIdx.x * 128;
    float acc[4][4][4] = {};

    for (int c = 0; c < (K >> 5); c++) {
        __syncthreads();
        ld_atile(Ah_, Al_, Ahi + (size_t)m0 * lda + c * 32,
                           Alo + (size_t)m0 * lda + c * 32, lda, tid);
        ld_bttile<128>(Bh_, Bl_, Whi + (size_t)(c * 32) * ldb + n0,
                                 Wlo + (size_t)(c * 32) * ldb + n0, ldb, tid);
        __syncthreads();
        mma_chunk<4, true, 128>(sb, sb + 8192, sb + 16384, sb + 24576, wm, wn, lane, acc);
    }

    #pragma unroll
    for (int mt = 0; mt < 4; mt++)
        #pragma unroll
        for (int nt = 0; nt < 4; nt++) {
            int n = n0 + wn * 32 + nt * 8 + (lane & 3) * 2;
            float bx = __ldg(bias + n), by = __ldg(bias + n + 1);
            #pragma unroll
            for (int hf = 0; hf < 2; hf++) {
                int m = m0 + wm * 64 + mt * 16 + (lane >> 2) + hf * 8;
                float v0 = acc[mt][nt][hf * 2]     + bx;
                float v1 = acc[mt][nt][hf * 2 + 1] + by;
                if (GELU) {
                    v0 = 0.5f * v0 * (1.f + erff(v0 * 0.7071067811865476f));
                    v1 = 0.5f * v1 * (1.f + erff(v1 * 0.7071067811865476f));
                }
                size_t off = (size_t)m * ldc + n;
                if (SPLITOUT) {
                    store_split2(ohi, olo, off, v0, v1);
                } else {
                    if (RESID) {
                        float2 r = *(const float2*)(resid + off);
                        v0 += r.x; v1 += r.y;
                    }
                    float2 o2; o2.x = v0; o2.y = v1;
                    *(float2*)(outf + off) = o2;
                }
            }
        }
}

/* ================= scores = mask(scale * Q K^T) ================= */
__global__ __launch_bounds__(256) void scores_gemm(
    const bf16* __restrict__ qhi, const bf16* __restrict__ qlo,
    const int* __restrict__ mask, float* __restrict__ sc)
{
    __shared__ __align__(1024) char sm[32768];
    char *Ah_ = sm, *Al_ = sm + 8192, *Bh_ = sm + 16384, *Bl_ = sm + 24576;
    uint32_t sb = smem_u32(sm);
    const int tid = threadIdx.x, lane = tid & 31, wid = tid >> 5;
    const int wm = wid >> 2, wn = wid & 3;
    const int z = blockIdx.z, b = z / NH, h = z % NH;
    const int m0 = blockIdx.y * 128, n0 = blockIdx.x * 128;
    const bf16* Qh = qhi + (size_t)b * SEQ * 2304 + h * 64;
    const bf16* Ql = qlo + (size_t)b * SEQ * 2304 + h * 64;
    float acc[4][4][4] = {};

    #pragma unroll
    for (int c = 0; c < 2; c++) {
        __syncthreads();
        ld_atile(Ah_, Al_, Qh + (size_t)m0 * 2304 + c * 32,
                           Ql + (size_t)m0 * 2304 + c * 32, 2304, tid);
        ld_atile(Bh_, Bl_, Qh + 768 + (size_t)n0 * 2304 + c * 32,
                           Ql + 768 + (size_t)n0 * 2304 + c * 32, 2304, tid);
        __syncthreads();
        mma_chunk<4, false, 128>(sb, sb + 8192, sb + 16384, sb + 24576, wm, wn, lane, acc);
    }

    const int* mb = mask + (size_t)b * SEQ * SEQ;
    float* Cz = sc + (size_t)z * SEQ * SEQ;
    #pragma unroll
    for (int mt = 0; mt < 4; mt++)
        #pragma unroll
        for (int nt = 0; nt < 4; nt++) {
            int n = n0 + wn * 32 + nt * 8 + (lane & 3) * 2;
            #pragma unroll
            for (int hf = 0; hf < 2; hf++) {
                int m = m0 + wm * 64 + mt * 16 + (lane >> 2) + hf * 8;
                int2 mm = *(const int2*)(mb + (size_t)m * SEQ + n);
                float2 o2;
                o2.x = mm.x ? acc[mt][nt][hf * 2]     * ATTN_SCALE : -10000.f;
                o2.y = mm.y ? acc[mt][nt][hf * 2 + 1] * ATTN_SCALE : -10000.f;
                *(float2*)(Cz + (size_t)m * SEQ + n) = o2;
            }
        }
}

/* ================= attn = P @ V  (N=64) ================= */
__global__ __launch_bounds__(256) void av_gemm(
    const bf16* __restrict__ phi, const bf16* __restrict__ plo,
    const bf16* __restrict__ qkvhi, const bf16* __restrict__ qkvlo,
    bf16* __restrict__ ohi, bf16* __restrict__ olo)
{
    __shared__ __align__(1024) char sm[24576];
    char *Ah_ = sm, *Al_ = sm + 8192, *Bh_ = sm + 16384, *Bl_ = sm + 20480;
    uint32_t sb = smem_u32(sm);
    const int tid = threadIdx.x, lane = tid & 31, wid = tid >> 5;
    const int wm = wid >> 1, wn = wid & 1;
    const int z = blockIdx.y, b = z / NH, h = z % NH;
    const int m0 = blockIdx.x * 128;
    const bf16* Ph = phi + (size_t)z * SEQ * SEQ;
    const bf16* Pl = plo + (size_t)z * SEQ * SEQ;
    const bf16* Vh = qkvhi + (size_t)b * SEQ * 2304 + 1536 + h * 64;
    const bf16* Vl = qkvlo + (size_t)b * SEQ * 2304 + 1536 + h * 64;
    float acc[2][4][4] = {};

    for (int c = 0; c < 64; c++) {
        __syncthreads();
        ld_atile(Ah_, Al_, Ph + (size_t)m0 * SEQ + c * 32,
                           Pl + (size_t)m0 * SEQ + c * 32, SEQ, tid);
        ld_bttile<64>(Bh_, Bl_, Vh + (size_t)(c * 32) * 2304,
                                Vl + (size_t)(c * 32) * 2304, 2304, tid);
        __syncthreads();
        mma_chunk<2, true, 64>(sb, sb + 8192, sb + 16384, sb + 20480, wm, wn, lane, acc);
    }

    #pragma unroll
    for (int mt = 0; mt < 2; mt++)
        #pragma unroll
        for (int nt = 0; nt < 4; nt++) {
            int col = h * 64 + wn * 32 + nt * 8 + (lane & 3) * 2;
            #pragma unroll
            for (int hf = 0; hf < 2; hf++) {
                int m = m0 + wm * 32 + mt * 16 + (lane >> 2) + hf * 8;
                size_t off = ((size_t)b * SEQ + m) * DIM + col;
                store_split2(ohi, olo, off, acc[mt][nt][hf * 2], acc[mt][nt][hf * 2 + 1]);
            }
        }
}

/* ================= driver ================= */
extern "C" void kernel_launch(void* const* d_in, const int* in_sizes, int n_in,
                              void* d_out, int out_size)
{
    const float* x      = (const float*)d_in[0];
    const int*   mask   = (const int*)  d_in[1];
    const float* w_qkv  = (const float*)d_in[2];
    const float* b_qkv  = (const float*)d_in[3];
    const float* w_proj = (const float*)d_in[4];
    const float* b_proj = (const float*)d_in[5];
    const float* g1     = (const float*)d_in[6];
    const float* beta1  = (const float*)d_in[7];
    const float* g2     = (const float*)d_in[8];
    const float* beta2  = (const float*)d_in[9];
    const float* w1     = (const float*)d_in[10];
    const float* b1     = (const float*)d_in[11];
    const float* w2     = (const float*)d_in[12];
    const float* b2     = (const float*)d_in[13];
    float* out = (float*)d_out;

    bf16 *hh, *hl, *qh, *ql, *Ph, *Pl, *ath, *atl, *h2h, *h2l, *ach, *acl;
    bf16 *wqh, *wql, *wph, *wpl, *w1h, *w1l, *w2h, *w2l;
    float *sc, *x1;
    cudaGetSymbolAddress((void**)&hh,  g_h_hi);   cudaGetSymbolAddress((void**)&hl,  g_h_lo);
    cudaGetSymbolAddress((void**)&qh,  g_qkv_hi); cudaGetSymbolAddress((void**)&ql,  g_qkv_lo);
    cudaGetSymbolAddress((void**)&sc,  g_sc);
    cudaGetSymbolAddress((void**)&Ph,  g_P_hi);   cudaGetSymbolAddress((void**)&Pl,  g_P_lo);
    cudaGetSymbolAddress((void**)&ath, g_at_hi);  cudaGetSymbolAddress((void**)&atl, g_at_lo);
    cudaGetSymbolAddress((void**)&x1,  g_x1);
    cudaGetSymbolAddress((void**)&h2h, g_h2_hi);  cudaGetSymbolAddress((void**)&h2l, g_h2_lo);
    cudaGetSymbolAddress((void**)&ach, g_ac_hi);  cudaGetSymbolAddress((void**)&acl, g_ac_lo);
    cudaGetSymbolAddress((void**)&wqh, g_wqkv_hi); cudaGetSymbolAddress((void**)&wql, g_wqkv_lo);
    cudaGetSymbolAddress((void**)&wph, g_wpr_hi);  cudaGetSymbolAddress((void**)&wpl, g_wpr_lo);
    cudaGetSymbolAddress((void**)&w1h, g_w1_hi);   cudaGetSymbolAddress((void**)&w1l, g_w1_lo);
    cudaGetSymbolAddress((void**)&w2h, g_w2_hi);   cudaGetSymbolAddress((void**)&w2l, g_w2_lo);

    wsplit<<<1728, 256>>>(w_qkv,  wqh, wql, 768 * 2304);
    wsplit<<<576,  256>>>(w_proj, wph, wpl, 768 * 768);
    wsplit<<<2304, 256>>>(w1,     w1h, w1l, 768 * 3072);
    wsplit<<<2304, 256>>>(w2,     w2h, w2l, 3072 * 768);

    ln_split<<<NT, 256>>>(x, g1, beta1, hh, hl);
    lin_gemm<false, false, true><<<dim3(18, 64), 256>>>(
        hh, hl, DIM, wqh, wql, 3 * DIM, b_qkv, nullptr,
        nullptr, qh, ql, 3 * DIM, DIM);
    scores_gemm<<<dim3(16, 16, NBH), 256>>>(qh, ql, mask, sc);
    softmax_split<<<NBH * SEQ, 256>>>(sc, Ph, Pl);
    av_gemm<<<dim3(16, NBH), 256>>>(Ph, Pl, qh, ql, ath, atl);
    lin_gemm<false, true, false><<<dim3(6, 64), 256>>>(
        ath, atl, DIM, wph, wpl, DIM, b_proj, x,
        x1, nullptr, nullptr, DIM, DIM);
    ln_split<<<NT, 256>>>(x1, g2, beta2, h2h, h2l);
    lin_gemm<true, false, true><<<dim3(24, 64), 256>>>(
        h2h, h2l, DIM, w1h, w1l, HID, b1, nullptr,
        nullptr, ach, acl, HID, DIM);
    lin_gemm<false, true, false><<<dim3(6, 64), 256>>>(
        ach, acl, HID, w2h, w2l, DIM, b2, x1,
        out, nullptr, nullptr, DIM, HID);
}

// round 7
// speedup vs baseline: 2.4658x; 1.1350x over previous
#include <cuda_runtime.h>
#include <cuda_bf16.h>
#include <math.h>
#include <cstdint>

#define DIM   768
#define NH    12
#define HD    64
#define HID   3072
#define BATCH 4
#define SEQ   2048
#define NT    (BATCH*SEQ)
#define NBH   (BATCH*NH)
#define ATTN_SCALE 0.125f

typedef __nv_bfloat16 bf16;

/* ---------------- scratch planes (device globals) ---------------- */
__device__ unsigned short g_h_hi [(size_t)NT * DIM],      g_h_lo [(size_t)NT * DIM];
__device__ unsigned short g_qkv_hi[(size_t)NT * 3 * DIM], g_qkv_lo[(size_t)NT * 3 * DIM];
__device__ unsigned short g_at_hi[(size_t)NT * DIM],      g_at_lo[(size_t)NT * DIM];
__device__ float          g_x1   [(size_t)NT * DIM];
__device__ unsigned short g_h2_hi[(size_t)NT * DIM],      g_h2_lo[(size_t)NT * DIM];
__device__ unsigned short g_ac_hi[(size_t)NT * HID],      g_ac_lo[(size_t)NT * HID];
__device__ unsigned short g_wqkv_hi[768*2304], g_wqkv_lo[768*2304];
__device__ unsigned short g_wpr_hi [768*768],  g_wpr_lo [768*768];
__device__ unsigned short g_w1_hi  [768*3072], g_w1_lo  [768*3072];
__device__ unsigned short g_w2_hi  [3072*768], g_w2_lo  [3072*768];

/* ---------------- mma / ldmatrix primitives ---------------- */
__device__ __forceinline__ uint32_t smem_u32(const void* p) {
    uint32_t a;
    asm("{ .reg .u64 t; cvta.to.shared.u64 t, %1; cvt.u32.u64 %0, t; }" : "=r"(a) : "l"(p));
    return a;
}
__device__ __forceinline__ void ldsm4(uint32_t* r, uint32_t a) {
    asm volatile("ldmatrix.sync.aligned.m8n8.x4.shared.b16 {%0,%1,%2,%3}, [%4];"
                 : "=r"(r[0]),"=r"(r[1]),"=r"(r[2]),"=r"(r[3]) : "r"(a));
}
__device__ __forceinline__ void ldsm2(uint32_t* r, uint32_t a) {
    asm volatile("ldmatrix.sync.aligned.m8n8.x2.shared.b16 {%0,%1}, [%2];"
                 : "=r"(r[0]),"=r"(r[1]) : "r"(a));
}
__device__ __forceinline__ void ldsm2t(uint32_t* r, uint32_t a) {
    asm volatile("ldmatrix.sync.aligned.m8n8.x2.trans.shared.b16 {%0,%1}, [%2];"
                 : "=r"(r[0]),"=r"(r[1]) : "r"(a));
}
__device__ __forceinline__ void mma_bf16(float* d, const uint32_t* a, const uint32_t* b) {
    asm volatile("mma.sync.aligned.m16n8k16.row.col.f32.bf16.bf16.f32 "
                 "{%0,%1,%2,%3}, {%4,%5,%6,%7}, {%8,%9}, {%0,%1,%2,%3};"
                 : "+f"(d[0]),"+f"(d[1]),"+f"(d[2]),"+f"(d[3])
                 : "r"(a[0]),"r"(a[1]),"r"(a[2]),"r"(a[3]),"r"(b[0]),"r"(b[1]));
}

/* smem layouts (validated R6):
   A-style tile [rows][32] bf16, 64B rows, swizzle c ^ ((r>>1)&3)  -> conflict-free ldmatrix
   B-trans tile [32][NTILE] bf16, swizzle c ^ (k&7)                -> conflict-free ldmatrix.trans */
__device__ __forceinline__ int a_off(int r, int c) { return r * 64 + ((c ^ ((r >> 1) & 3)) << 4); }
template<int NTILE>
__device__ __forceinline__ int bt_off(int k, int c) { return k * (NTILE * 2) + ((c ^ (k & 7)) << 4); }

/* global -> smem tile loaders (hi+lo planes) */
__device__ __forceinline__ void ld_atile(char* dh, char* dl,
    const bf16* gh, const bf16* gl, int stride, int tid)
{
    int row = tid >> 1, cp = (tid & 1) * 2;
    size_t o = (size_t)row * stride + cp * 8;
    uint4 h0 = *(const uint4*)(gh + o), h1 = *(const uint4*)(gh + o + 8);
    uint4 l0 = *(const uint4*)(gl + o), l1 = *(const uint4*)(gl + o + 8);
    *(uint4*)(dh + a_off(row, cp))     = h0;
    *(uint4*)(dh + a_off(row, cp + 1)) = h1;
    *(uint4*)(dl + a_off(row, cp))     = l0;
    *(uint4*)(dl + a_off(row, cp + 1)) = l1;
}
template<int NTILE>
__device__ __forceinline__ void ld_bttile(char* dh, char* dl,
    const bf16* gh, const bf16* gl, int ldb, int tid)
{
    int k = tid >> 3, cb = tid & 7;
    size_t o = (size_t)k * ldb + cb * 8;
    uint4 h0 = *(const uint4*)(gh + o);
    uint4 l0 = *(const uint4*)(gl + o);
    *(uint4*)(dh + bt_off<NTILE>(k, cb)) = h0;
    *(uint4*)(dl + bt_off<NTILE>(k, cb)) = l0;
    if (NTILE == 128) {
        uint4 h1 = *(const uint4*)(gh + o + 64);
        uint4 l1 = *(const uint4*)(gl + o + 64);
        *(uint4*)(dh + bt_off<NTILE>(k, cb + 8)) = h1;
        *(uint4*)(dl + bt_off<NTILE>(k, cb + 8)) = l1;
    }
}

/* one BK=32 chunk of split-mma: acc += Ah*Bh + Ah*Bl + Al*Bh */
template<int MT, bool BTRANS, int NTILE>
__device__ __forceinline__ void mma_chunk(
    uint32_t sAh, uint32_t sAl, uint32_t sBh, uint32_t sBl,
    int wm, int wn, int lane, float acc[][4][4])
{
    const int jA = lane >> 3, rA = lane & 7;
    const int jB = (lane >> 3) & 1, rB = lane & 7;
    #pragma unroll
    for (int ks = 0; ks < 32; ks += 16) {
        uint32_t Ah[MT][4], Al[MT][4], Bh[4][2], Bl[4][2];
        #pragma unroll
        for (int mt = 0; mt < MT; mt++) {
            int row = wm * MT * 16 + mt * 16 + (jA & 1) * 8 + rA;
            int cc  = (ks >> 3) + (jA >> 1);
            ldsm4(Ah[mt], sAh + a_off(row, cc));
            ldsm4(Al[mt], sAl + a_off(row, cc));
        }
        #pragma unroll
        for (int nt = 0; nt < 4; nt++) {
            if (BTRANS) {
                int krow = ks + jB * 8 + rB;
                int cc   = (wn * 32 + nt * 8) >> 3;
                ldsm2t(Bh[nt], sBh + bt_off<NTILE>(krow, cc));
                ldsm2t(Bl[nt], sBl + bt_off<NTILE>(krow, cc));
            } else {
                int nrow = wn * 32 + nt * 8 + rB;
                int cc   = (ks >> 3) + jB;
                ldsm2(Bh[nt], sBh + a_off(nrow, cc));
                ldsm2(Bl[nt], sBl + a_off(nrow, cc));
            }
        }
        #pragma unroll
        for (int mt = 0; mt < MT; mt++)
            #pragma unroll
            for (int nt = 0; nt < 4; nt++) {
                mma_bf16(acc[mt][nt], Ah[mt], Bh[nt]);
                mma_bf16(acc[mt][nt], Ah[mt], Bl[nt]);
                mma_bf16(acc[mt][nt], Al[mt], Bh[nt]);
            }
    }
}

__device__ __forceinline__ void split2w(float a, float b, uint32_t& hi, uint32_t& lo)
{
    bf16 h0 = __float2bfloat16(a), h1 = __float2bfloat16(b);
    bf16 l0 = __float2bfloat16(a - __bfloat162float(h0));
    bf16 l1 = __float2bfloat16(b - __bfloat162float(h1));
    hi = (uint32_t)__bfloat16_as_ushort(h0) | ((uint32_t)__bfloat16_as_ushort(h1) << 16);
    lo = (uint32_t)__bfloat16_as_ushort(l0) | ((uint32_t)__bfloat16_as_ushort(l1) << 16);
}
__device__ __forceinline__ void store_split2(bf16* hi, bf16* lo, size_t off,
                                             float v0, float v1)
{
    uint32_t H, L;
    split2w(v0, v1, H, L);
    *(uint32_t*)(hi + off) = H;
    *(uint32_t*)(lo + off) = L;
}

/* ================= layernorm -> split planes ================= */
__global__ __launch_bounds__(256) void ln_split(
    const float* __restrict__ x, const float* __restrict__ gamma,
    const float* __restrict__ beta, bf16* __restrict__ ohi, bf16* __restrict__ olo)
{
    int row = blockIdx.x;
    const float* xr = x + (size_t)row * DIM;
    float s = 0.f, s2 = 0.f;
    for (int i = threadIdx.x; i < DIM; i += 256) { float v = xr[i]; s += v; s2 += v * v; }
    __shared__ float sh[64];
    #pragma unroll
    for (int o = 16; o > 0; o >>= 1) {
        s  += __shfl_xor_sync(0xffffffffu, s,  o);
        s2 += __shfl_xor_sync(0xffffffffu, s2, o);
    }
    int warp = threadIdx.x >> 5, lane = threadIdx.x & 31;
    if (lane == 0) { sh[warp] = s; sh[warp + 32] = s2; }
    __syncthreads();
    if (threadIdx.x < 32) {
        s  = (threadIdx.x < 8) ? sh[threadIdx.x]      : 0.f;
        s2 = (threadIdx.x < 8) ? sh[threadIdx.x + 32] : 0.f;
        #pragma unroll
        for (int o = 4; o > 0; o >>= 1) {
            s  += __shfl_xor_sync(0xffffffffu, s,  o);
            s2 += __shfl_xor_sync(0xffffffffu, s2, o);
        }
        if (lane == 0) { sh[0] = s; sh[1] = s2; }
    }
    __syncthreads();
    float mu  = sh[0] * (1.f / DIM);
    float inv = rsqrtf(sh[1] * (1.f / DIM) - mu * mu + 1e-6f);
    for (int i = threadIdx.x; i < DIM; i += 256) {
        float v = (xr[i] - mu) * inv * gamma[i] + beta[i];
        bf16 h = __float2bfloat16(v);
        ohi[(size_t)row * DIM + i] = h;
        olo[(size_t)row * DIM + i] = __float2bfloat16(v - __bfloat162float(h));
    }
}

/* ================= weight split ================= */
__global__ __launch_bounds__(256) void wsplit(
    const float* __restrict__ src, bf16* __restrict__ hi, bf16* __restrict__ lo, int n)
{
    int i = (blockIdx.x * 256 + threadIdx.x) * 4;
    if (i >= n) return;
    float4 v = *(const float4*)(src + i);
    store_split2(hi, lo, i,     v.x, v.y);
    store_split2(hi, lo, i + 2, v.z, v.w);
}

/* ================= fused flash attention =================
   one CTA: one (b,h), 128 q rows. k-tiles of 64, online softmax.
   smem: loop phase K: Kh0@0 Kh1@4K Kl0@8K Kl1@12K (64rx32c a_off tiles)
                    V: Vh0@16K Vh1@20K Vl0@24K Vl1@28K (bt_off<64>, 32k chunks)
         Q staging (once): Qh0@0 Qh1@8K Ql0@16K Ql1@24K (128r tiles) */
__global__ __launch_bounds__(256) void flash_attn(
    const bf16* __restrict__ qhi, const bf16* __restrict__ qlo,
    const int* __restrict__ mask,
    bf16* __restrict__ ohi, bf16* __restrict__ olo)
{
    __shared__ __align__(1024) char sm[32768];
    uint32_t sb = smem_u32(sm);
    const int tid = threadIdx.x, lane = tid & 31, w = tid >> 5;
    const int z = blockIdx.y, b = z / NH, h = z % NH;
    const int m0 = blockIdx.x * 128;
    const int jA = lane >> 3, rA = lane & 7;
    const int jB = (lane >> 3) & 1, rB = lane & 7;

    /* stage Q (128x64) then pull into registers */
    {
        const bf16* Qg_h = qhi + (size_t)(b * SEQ + m0) * 2304 + h * 64;
        const bf16* Qg_l = qlo + (size_t)(b * SEQ + m0) * 2304 + h * 64;
        ld_atile(sm,        sm + 16384, Qg_h,      Qg_l,      2304, tid);
        ld_atile(sm + 8192, sm + 24576, Qg_h + 32, Qg_l + 32, 2304, tid);
    }
    __syncthreads();
    uint32_t qfh[4][4], qfl[4][4];
    #pragma unroll
    for (int ks = 0; ks < 4; ks++) {
        int off = (ks >> 1) * 8192 + a_off(w * 16 + (jA & 1) * 8 + rA, ((ks & 1) << 1) + (jA >> 1));
        ldsm4(qfh[ks], sb + off);
        ldsm4(qfl[ks], sb + 16384 + off);
    }

    float oacc[8][4] = {};
    float m_a = -1e30f, m_b = -1e30f, l_a = 0.f, l_b = 0.f;
    const int* mrow_a = mask + (size_t)b * SEQ * SEQ + (size_t)(m0 + w * 16 + (lane >> 2)) * SEQ;
    const int* mrow_b = mrow_a + 8 * SEQ;

    for (int kt = 0; kt < SEQ / 64; kt++) {
        __syncthreads();
        {   /* K tile 64x64 (2 chunks of 32 cols) */
            int row = tid >> 2, c = tid & 3;
            const bf16* Kg_h = qhi + (size_t)(b * SEQ + kt * 64 + row) * 2304 + 768 + h * 64;
            const bf16* Kg_l = qlo + (size_t)(b * SEQ + kt * 64 + row) * 2304 + 768 + h * 64;
            *(uint4*)(sm +     0 + a_off(row, c)) = *(const uint4*)(Kg_h + c * 8);
            *(uint4*)(sm +  4096 + a_off(row, c)) = *(const uint4*)(Kg_h + 32 + c * 8);
            *(uint4*)(sm +  8192 + a_off(row, c)) = *(const uint4*)(Kg_l + c * 8);
            *(uint4*)(sm + 12288 + a_off(row, c)) = *(const uint4*)(Kg_l + 32 + c * 8);
        }
        {   /* V tile 64k x 64n (2 k-chunks of 32) */
            int kr = tid >> 3, cb = tid & 7;
            const bf16* Vg_h = qhi + (size_t)(b * SEQ + kt * 64 + kr) * 2304 + 1536 + h * 64 + cb * 8;
            const bf16* Vg_l = qlo + (size_t)(b * SEQ + kt * 64 + kr) * 2304 + 1536 + h * 64 + cb * 8;
            *(uint4*)(sm + 16384 + bt_off<64>(kr, cb)) = *(const uint4*)(Vg_h);
            *(uint4*)(sm + 20480 + bt_off<64>(kr, cb)) = *(const uint4*)(Vg_h + 32 * 2304);
            *(uint4*)(sm + 24576 + bt_off<64>(kr, cb)) = *(const uint4*)(Vg_l);
            *(uint4*)(sm + 28672 + bt_off<64>(kr, cb)) = *(const uint4*)(Vg_l + 32 * 2304);
        }
        __syncthreads();

        /* S = Q K^T (3-term split) */
        float sacc[8][4] = {};
        #pragma unroll
        for (int ks = 0; ks < 4; ks++) {
            int cbase = (ks >> 1) * 4096;
            int cc = ((ks & 1) << 1) + jB;
            #pragma unroll
            for (int nt = 0; nt < 8; nt++) {
                uint32_t Bh[2], Bl[2];
                int ao = a_off(nt * 8 + rB, cc);
                ldsm2(Bh, sb + cbase + ao);
                ldsm2(Bl, sb + 8192 + cbase + ao);
                mma_bf16(sacc[nt], qfh[ks], Bh);
                mma_bf16(sacc[nt], qfh[ks], Bl);
                mma_bf16(sacc[nt], qfl[ks], Bh);
            }
        }

        /* mask + scale + online softmax */
        const int* mka = mrow_a + kt * 64 + (lane & 3) * 2;
        const int* mkb = mrow_b + kt * 64 + (lane & 3) * 2;
        float mx_a = -1e30f, mx_b = -1e30f;
        #pragma unroll
        for (int nt = 0; nt < 8; nt++) {
            int2 ma = *(const int2*)(mka + nt * 8);
            int2 mb = *(const int2*)(mkb + nt * 8);
            sacc[nt][0] = ma.x ? sacc[nt][0] * ATTN_SCALE : -10000.f;
            sacc[nt][1] = ma.y ? sacc[nt][1] * ATTN_SCALE : -10000.f;
            sacc[nt][2] = mb.x ? sacc[nt][2] * ATTN_SCALE : -10000.f;
            sacc[nt][3] = mb.y ? sacc[nt][3] * ATTN_SCALE : -10000.f;
            mx_a = fmaxf(mx_a, fmaxf(sacc[nt][0], sacc[nt][1]));
            mx_b = fmaxf(mx_b, fmaxf(sacc[nt][2], sacc[nt][3]));
        }
        mx_a = fmaxf(mx_a, __shfl_xor_sync(0xffffffffu, mx_a, 1));
        mx_a = fmaxf(mx_a, __shfl_xor_sync(0xffffffffu, mx_a, 2));
        mx_b = fmaxf(mx_b, __shfl_xor_sync(0xffffffffu, mx_b, 1));
        mx_b = fmaxf(mx_b, __shfl_xor_sync(0xffffffffu, mx_b, 2));
        float mn_a = fmaxf(m_a, mx_a), mn_b = fmaxf(m_b, mx_b);
        float al_a = __expf(m_a - mn_a), al_b = __expf(m_b - mn_b);
        m_a = mn_a; m_b = mn_b;
        float s_a = 0.f, s_b = 0.f;
        #pragma unroll
        for (int nt = 0; nt < 8; nt++) {
            sacc[nt][0] = __expf(sacc[nt][0] - mn_a);
            sacc[nt][1] = __expf(sacc[nt][1] - mn_a);
            sacc[nt][2] = __expf(sacc[nt][2] - mn_b);
            sacc[nt][3] = __expf(sacc[nt][3] - mn_b);
            s_a += sacc[nt][0] + sacc[nt][1];
            s_b += sacc[nt][2] + sacc[nt][3];
        }
        s_a += __shfl_xor_sync(0xffffffffu, s_a, 1);
        s_a += __shfl_xor_sync(0xffffffffu, s_a, 2);
        s_b += __shfl_xor_sync(0xffffffffu, s_b, 1);
        s_b += __shfl_xor_sync(0xffffffffu, s_b, 2);
        l_a = al_a * l_a + s_a;
        l_b = al_b * l_b + s_b;
        #pragma unroll
        for (int nt = 0; nt < 8; nt++) {
            oacc[nt][0] *= al_a; oacc[nt][1] *= al_a;
            oacc[nt][2] *= al_b; oacc[nt][3] *= al_b;
        }

        /* O += P V (P re-split hi/lo in registers) */
        #pragma unroll
        for (int ks = 0; ks < 4; ks++) {
            uint32_t ph[4], pl[4];
            split2w(sacc[2*ks  ][0], sacc[2*ks  ][1], ph[0], pl[0]);
            split2w(sacc[2*ks  ][2], sacc[2*ks  ][3], ph[1], pl[1]);
            split2w(sacc[2*ks+1][0], sacc[2*ks+1][1], ph[2], pl[2]);
            split2w(sacc[2*ks+1][2], sacc[2*ks+1][3], ph[3], pl[3]);
            int cbase = (ks >> 1) * 4096;
            int krow = (ks & 1) * 16 + jB * 8 + rB;
            #pragma unroll
            for (int nt = 0; nt < 8; nt++) {
                uint32_t Vh[2], Vl[2];
                int vo = bt_off<64>(krow, nt);
                ldsm2t(Vh, sb + 16384 + cbase + vo);
                ldsm2t(Vl, sb + 24576 + cbase + vo);
                mma_bf16(oacc[nt], ph, Vh);
                mma_bf16(oacc[nt], ph, Vl);
                mma_bf16(oacc[nt], pl, Vh);
            }
        }
    }

    /* epilogue: O / l -> split planes */
    float inv_a = 1.f / l_a, inv_b = 1.f / l_b;
    #pragma unroll
    for (int nt = 0; nt < 8; nt++) {
        int col = h * 64 + nt * 8 + (lane & 3) * 2;
        size_t off = (size_t)(b * SEQ + m0 + w * 16 + (lane >> 2)) * DIM + col;
        store_split2(ohi, olo, off,           oacc[nt][0] * inv_a, oacc[nt][1] * inv_a);
        store_split2(ohi, olo, off + 8 * DIM, oacc[nt][2] * inv_b, oacc[nt][3] * inv_b);
    }
}

/* ================= linear GEMM: C = A@W (+bias)(gelu)(+resid) ================= */
template<bool GELU, bool RESID, bool SPLITOUT>
__global__ __launch_bounds__(256) void lin_gemm(
    const bf16* __restrict__ Ahi, const bf16* __restrict__ Alo, int lda,
    const bf16* __restrict__ Whi, const bf16* __restrict__ Wlo, int ldb,
    const float* __restrict__ bias, const float* __restrict__ resid,
    float* __restrict__ outf, bf16* __restrict__ ohi, bf16* __restrict__ olo,
    int ldc, int K)
{
    __shared__ __align__(1024) char sm[32768];
    char *Ah_ = sm, *Al_ = sm + 8192, *Bh_ = sm + 16384, *Bl_ = sm + 24576;
    uint32_t sb = smem_u32(sm);
    const int tid = threadIdx.x, lane = tid & 31, wid = tid >> 5;
    const int wm = wid >> 2, wn = wid & 3;
    const int m0 = blockIdx.y * 128, n0 = blockIdx.x * 128;
    float acc[4][4][4] = {};

    for (int c = 0; c < (K >> 5); c++) {
        __syncthreads();
        ld_atile(Ah_, Al_, Ahi + (size_t)m0 * lda + c * 32,
                           Alo + (size_t)m0 * lda + c * 32, lda, tid);
        ld_bttile<128>(Bh_, Bl_, Whi + (size_t)(c * 32) * ldb + n0,
                                 Wlo + (size_t)(c * 32) * ldb + n0, ldb, tid);
        __syncthreads();
        mma_chunk<4, true, 128>(sb, sb + 8192, sb + 16384, sb + 24576, wm, wn, lane, acc);
    }

    #pragma unroll
    for (int mt = 0; mt < 4; mt++)
        #pragma unroll
        for (int nt = 0; nt < 4; nt++) {
            int n = n0 + wn * 32 + nt * 8 + (lane & 3) * 2;
            float bx = __ldg(bias + n), by = __ldg(bias + n + 1);
            #pragma unroll
            for (int hf = 0; hf < 2; hf++) {
                int m = m0 + wm * 64 + mt * 16 + (lane >> 2) + hf * 8;
                float v0 = acc[mt][nt][hf * 2]     + bx;
                float v1 = acc[mt][nt][hf * 2 + 1] + by;
                if (GELU) {
                    v0 = 0.5f * v0 * (1.f + erff(v0 * 0.7071067811865476f));
                    v1 = 0.5f * v1 * (1.f + erff(v1 * 0.7071067811865476f));
                }
                size_t off = (size_t)m * ldc + n;
                if (SPLITOUT) {
                    store_split2(ohi, olo, off, v0, v1);
                } else {
                    if (RESID) {
                        float2 r = *(const float2*)(resid + off);
                        v0 += r.x; v1 += r.y;
                    }
                    float2 o2; o2.x = v0; o2.y = v1;
                    *(float2*)(outf + off) = o2;
                }
            }
        }
}

/* ================= driver ================= */
extern "C" void kernel_launch(void* const* d_in, const int* in_sizes, int n_in,
                              void* d_out, int out_size)
{
    const float* x      = (const float*)d_in[0];
    const int*   mask   = (const int*)  d_in[1];
    const float* w_qkv  = (const float*)d_in[2];
    const float* b_qkv  = (const float*)d_in[3];
    const float* w_proj = (const float*)d_in[4];
    const float* b_proj = (const float*)d_in[5];
    const float* g1     = (const float*)d_in[6];
    const float* beta1  = (const float*)d_in[7];
    const float* g2     = (const float*)d_in[8];
    const float* beta2  = (const float*)d_in[9];
    const float* w1     = (const float*)d_in[10];
    const float* b1     = (const float*)d_in[11];
    const float* w2     = (const float*)d_in[12];
    const float* b2     = (const float*)d_in[13];
    float* out = (float*)d_out;

    bf16 *hh, *hl, *qh, *ql, *ath, *atl, *h2h, *h2l, *ach, *acl;
    bf16 *wqh, *wql, *wph, *wpl, *w1h, *w1l, *w2h, *w2l;
    float *x1;
    cudaGetSymbolAddress((void**)&hh,  g_h_hi);   cudaGetSymbolAddress((void**)&hl,  g_h_lo);
    cudaGetSymbolAddress((void**)&qh,  g_qkv_hi); cudaGetSymbolAddress((void**)&ql,  g_qkv_lo);
    cudaGetSymbolAddress((void**)&ath, g_at_hi);  cudaGetSymbolAddress((void**)&atl, g_at_lo);
    cudaGetSymbolAddress((void**)&x1,  g_x1);
    cudaGetSymbolAddress((void**)&h2h, g_h2_hi);  cudaGetSymbolAddress((void**)&h2l, g_h2_lo);
    cudaGetSymbolAddress((void**)&ach, g_ac_hi);  cudaGetSymbolAddress((void**)&acl, g_ac_lo);
    cudaGetSymbolAddress((void**)&wqh, g_wqkv_hi); cudaGetSymbolAddress((void**)&wql, g_wqkv_lo);
    cudaGetSymbolAddress((void**)&wph, g_wpr_hi);  cudaGetSymbolAddress((void**)&wpl, g_wpr_lo);
    cudaGetSymbolAddress((void**)&w1h, g_w1_hi);   cudaGetSymbolAddress((void**)&w1l, g_w1_lo);
    cudaGetSymbolAddress((void**)&w2h, g_w2_hi);   cudaGetSymbolAddress((void**)&w2l, g_w2_lo);

    wsplit<<<1728, 256>>>(w_qkv,  wqh, wql, 768 * 2304);
    wsplit<<<576,  256>>>(w_proj, wph, wpl, 768 * 768);
    wsplit<<<2304, 256>>>(w1,     w1h, w1l, 768 * 3072);
    wsplit<<<2304, 256>>>(w2,     w2h, w2l, 3072 * 768);

    ln_split<<<NT, 256>>>(x, g1, beta1, hh, hl);
    lin_gemm<false, false, true><<<dim3(18, 64), 256>>>(
        hh, hl, DIM, wqh, wql, 3 * DIM, b_qkv, nullptr,
        nullptr, qh, ql, 3 * DIM, DIM);
    flash_attn<<<dim3(16, NBH), 256>>>(qh, ql, mask, ath, atl);
    lin_gemm<false, true, false><<<dim3(6, 64), 256>>>(
        ath, atl, DIM, wph, wpl, DIM, b_proj, x,
        x1, nullptr, nullptr, DIM, DIM);
    ln_split<<<NT, 256>>>(x1, g2, beta2, h2h, h2l);
    lin_gemm<true, false, true><<<dim3(24, 64), 256>>>(
        h2h, h2l, DIM, w1h, w1l, HID, b1, nullptr,
        nullptr, ach, acl, HID, DIM);
    lin_gemm<false, true, false><<<dim3(6, 64), 256>>>(
        ach, acl, HID, w2h, w2l, DIM, b2, x1,
        out, nullptr, nullptr, DIM, HID);
}

// round 8
// speedup vs baseline: 2.7743x; 1.1251x over previous
#include <cuda_runtime.h>
#include <cuda_bf16.h>
#include <math.h>
#include <cstdint>

#define DIM   768
#define NH    12
#define HD    64
#define HID   3072
#define BATCH 4
#define SEQ   2048
#define NT    (BATCH*SEQ)
#define NBH   (BATCH*NH)
#define ATTN_SCALE 0.125f

typedef __nv_bfloat16 bf16;

/* ---------------- scratch planes (device globals) ---------------- */
__device__ unsigned short g_h_hi [(size_t)NT * DIM],      g_h_lo [(size_t)NT * DIM];
__device__ unsigned short g_qkv_hi[(size_t)NT * 3 * DIM], g_qkv_lo[(size_t)NT * 3 * DIM];
__device__ unsigned short g_at_hi[(size_t)NT * DIM],      g_at_lo[(size_t)NT * DIM];
__device__ float          g_x1   [(size_t)NT * DIM];
__device__ unsigned short g_h2_hi[(size_t)NT * DIM],      g_h2_lo[(size_t)NT * DIM];
__device__ unsigned short g_ac_hi[(size_t)NT * HID],      g_ac_lo[(size_t)NT * HID];
__device__ unsigned short g_wqkv_hi[768*2304], g_wqkv_lo[768*2304];
__device__ unsigned short g_wpr_hi [768*768],  g_wpr_lo [768*768];
__device__ unsigned short g_w1_hi  [768*3072], g_w1_lo  [768*3072];
__device__ unsigned short g_w2_hi  [3072*768], g_w2_lo  [3072*768];

/* ---------------- primitives ---------------- */
__device__ __forceinline__ uint32_t smem_u32(const void* p) {
    uint32_t a;
    asm("{ .reg .u64 t; cvta.to.shared.u64 t, %1; cvt.u32.u64 %0, t; }" : "=r"(a) : "l"(p));
    return a;
}
__device__ __forceinline__ void ldsm4(uint32_t* r, uint32_t a) {
    asm volatile("ldmatrix.sync.aligned.m8n8.x4.shared.b16 {%0,%1,%2,%3}, [%4];"
                 : "=r"(r[0]),"=r"(r[1]),"=r"(r[2]),"=r"(r[3]) : "r"(a));
}
__device__ __forceinline__ void ldsm2(uint32_t* r, uint32_t a) {
    asm volatile("ldmatrix.sync.aligned.m8n8.x2.shared.b16 {%0,%1}, [%2];"
                 : "=r"(r[0]),"=r"(r[1]) : "r"(a));
}
__device__ __forceinline__ void ldsm2t(uint32_t* r, uint32_t a) {
    asm volatile("ldmatrix.sync.aligned.m8n8.x2.trans.shared.b16 {%0,%1}, [%2];"
                 : "=r"(r[0]),"=r"(r[1]) : "r"(a));
}
__device__ __forceinline__ void mma_bf16(float* d, const uint32_t* a, const uint32_t* b) {
    asm volatile("mma.sync.aligned.m16n8k16.row.col.f32.bf16.bf16.f32 "
                 "{%0,%1,%2,%3}, {%4,%5,%6,%7}, {%8,%9}, {%0,%1,%2,%3};"
                 : "+f"(d[0]),"+f"(d[1]),"+f"(d[2]),"+f"(d[3])
                 : "r"(a[0]),"r"(a[1]),"r"(a[2]),"r"(a[3]),"r"(b[0]),"r"(b[1]));
}
__device__ __forceinline__ void cpa16(uint32_t dst, const void* src) {
    asm volatile("cp.async.cg.shared.global [%0], [%1], 16;" :: "r"(dst), "l"(src));
}
#define CP_COMMIT() asm volatile("cp.async.commit_group;" ::: "memory")
#define CP_WAIT(n)  asm volatile("cp.async.wait_group %0;" :: "n"(n) : "memory")

/* smem layouts (validated R6/R7):
   A-style tile [rows][32] bf16, 64B rows, swizzle c ^ ((r>>1)&3)
   B-trans tile [32][NTILE] bf16, swizzle c ^ (k&7) */
__device__ __forceinline__ int a_off(int r, int c) { return r * 64 + ((c ^ ((r >> 1) & 3)) << 4); }
template<int NTILE>
__device__ __forceinline__ int bt_off(int k, int c) { return k * (NTILE * 2) + ((c ^ (k & 7)) << 4); }

/* async global -> smem tile loaders (hi+lo planes) */
__device__ __forceinline__ void ld_atile_a(uint32_t dh, uint32_t dl,
    const bf16* gh, const bf16* gl, int stride, int tid)
{
    int row = tid >> 1, cp = (tid & 1) * 2;
    size_t o = (size_t)row * stride + cp * 8;
    cpa16(dh + a_off(row, cp),     gh + o);
    cpa16(dh + a_off(row, cp + 1), gh + o + 8);
    cpa16(dl + a_off(row, cp),     gl + o);
    cpa16(dl + a_off(row, cp + 1), gl + o + 8);
}
template<int NTILE>
__device__ __forceinline__ void ld_bttile_a(uint32_t dh, uint32_t dl,
    const bf16* gh, const bf16* gl, int ldb, int tid)
{
    int k = tid >> 3, cb = tid & 7;
    size_t o = (size_t)k * ldb + cb * 8;
    cpa16(dh + bt_off<NTILE>(k, cb), gh + o);
    cpa16(dl + bt_off<NTILE>(k, cb), gl + o);
    if (NTILE == 128) {
        cpa16(dh + bt_off<NTILE>(k, cb + 8), gh + o + 64);
        cpa16(dl + bt_off<NTILE>(k, cb + 8), gl + o + 64);
    }
}

/* one BK=32 chunk of split-mma: acc += Ah*Bh + Ah*Bl + Al*Bh */
template<int MT, bool BTRANS, int NTILE>
__device__ __forceinline__ void mma_chunk(
    uint32_t sAh, uint32_t sAl, uint32_t sBh, uint32_t sBl,
    int wm, int wn, int lane, float acc[][4][4])
{
    const int jA = lane >> 3, rA = lane & 7;
    const int jB = (lane >> 3) & 1, rB = lane & 7;
    #pragma unroll
    for (int ks = 0; ks < 32; ks += 16) {
        uint32_t Ah[MT][4], Al[MT][4], Bh[4][2], Bl[4][2];
        #pragma unroll
        for (int mt = 0; mt < MT; mt++) {
            int row = wm * MT * 16 + mt * 16 + (jA & 1) * 8 + rA;
            int cc  = (ks >> 3) + (jA >> 1);
            ldsm4(Ah[mt], sAh + a_off(row, cc));
            ldsm4(Al[mt], sAl + a_off(row, cc));
        }
        #pragma unroll
        for (int nt = 0; nt < 4; nt++) {
            if (BTRANS) {
                int krow = ks + jB * 8 + rB;
                int cc   = (wn * 32 + nt * 8) >> 3;
                ldsm2t(Bh[nt], sBh + bt_off<NTILE>(krow, cc));
                ldsm2t(Bl[nt], sBl + bt_off<NTILE>(krow, cc));
            } else {
                int nrow = wn * 32 + nt * 8 + rB;
                int cc   = (ks >> 3) + jB;
                ldsm2(Bh[nt], sBh + a_off(nrow, cc));
                ldsm2(Bl[nt], sBl + a_off(nrow, cc));
            }
        }
        #pragma unroll
        for (int mt = 0; mt < MT; mt++)
            #pragma unroll
            for (int nt = 0; nt < 4; nt++) {
                mma_bf16(acc[mt][nt], Ah[mt], Bh[nt]);
                mma_bf16(acc[mt][nt], Ah[mt], Bl[nt]);
                mma_bf16(acc[mt][nt], Al[mt], Bh[nt]);
            }
    }
}

__device__ __forceinline__ void split2w(float a, float b, uint32_t& hi, uint32_t& lo)
{
    bf16 h0 = __float2bfloat16(a), h1 = __float2bfloat16(b);
    bf16 l0 = __float2bfloat16(a - __bfloat162float(h0));
    bf16 l1 = __float2bfloat16(b - __bfloat162float(h1));
    hi = (uint32_t)__bfloat16_as_ushort(h0) | ((uint32_t)__bfloat16_as_ushort(h1) << 16);
    lo = (uint32_t)__bfloat16_as_ushort(l0) | ((uint32_t)__bfloat16_as_ushort(l1) << 16);
}
__device__ __forceinline__ void store_split2(bf16* hi, bf16* lo, size_t off,
                                             float v0, float v1)
{
    uint32_t H, L;
    split2w(v0, v1, H, L);
    *(uint32_t*)(hi + off) = H;
    *(uint32_t*)(lo + off) = L;
}

/* ================= layernorm -> split planes ================= */
__global__ __launch_bounds__(256) void ln_split(
    const float* __restrict__ x, const float* __restrict__ gamma,
    const float* __restrict__ beta, bf16* __restrict__ ohi, bf16* __restrict__ olo)
{
    int row = blockIdx.x;
    const float* xr = x + (size_t)row * DIM;
    float s = 0.f, s2 = 0.f;
    for (int i = threadIdx.x; i < DIM; i += 256) { float v = xr[i]; s += v; s2 += v * v; }
    __shared__ float sh[64];
    #pragma unroll
    for (int o = 16; o > 0; o >>= 1) {
        s  += __shfl_xor_sync(0xffffffffu, s,  o);
        s2 += __shfl_xor_sync(0xffffffffu, s2, o);
    }
    int warp = threadIdx.x >> 5, lane = threadIdx.x & 31;
    if (lane == 0) { sh[warp] = s; sh[warp + 32] = s2; }
    __syncthreads();
    if (threadIdx.x < 32) {
        s  = (threadIdx.x < 8) ? sh[threadIdx.x]      : 0.f;
        s2 = (threadIdx.x < 8) ? sh[threadIdx.x + 32] : 0.f;
        #pragma unroll
        for (int o = 4; o > 0; o >>= 1) {
            s  += __shfl_xor_sync(0xffffffffu, s,  o);
            s2 += __shfl_xor_sync(0xffffffffu, s2, o);
        }
        if (lane == 0) { sh[0] = s; sh[1] = s2; }
    }
    __syncthreads();
    float mu  = sh[0] * (1.f / DIM);
    float inv = rsqrtf(sh[1] * (1.f / DIM) - mu * mu + 1e-6f);
    for (int i = threadIdx.x; i < DIM; i += 256) {
        float v = (xr[i] - mu) * inv * gamma[i] + beta[i];
        bf16 h = __float2bfloat16(v);
        ohi[(size_t)row * DIM + i] = h;
        olo[(size_t)row * DIM + i] = __float2bfloat16(v - __bfloat162float(h));
    }
}

/* ================= weight split ================= */
__global__ __launch_bounds__(256) void wsplit(
    const float* __restrict__ src, bf16* __restrict__ hi, bf16* __restrict__ lo, int n)
{
    int i = (blockIdx.x * 256 + threadIdx.x) * 4;
    if (i >= n) return;
    float4 v = *(const float4*)(src + i);
    store_split2(hi, lo, i,     v.x, v.y);
    store_split2(hi, lo, i + 2, v.z, v.w);
}

/* ================= fused flash attention (cp.async 2-stage) ================= */
__global__ __launch_bounds__(256) void flash_attn(
    const bf16* __restrict__ qhi, const bf16* __restrict__ qlo,
    const int* __restrict__ mask,
    bf16* __restrict__ ohi, bf16* __restrict__ olo)
{
    extern __shared__ __align__(1024) char smx[];
    uint32_t sb = smem_u32(smx);
    const int tid = threadIdx.x, lane = tid & 31, w = tid >> 5;
    const int z = blockIdx.y, b = z / NH, h = z % NH;
    const int m0 = blockIdx.x * 128;
    const int jA = lane >> 3, rA = lane & 7;
    const int jB = (lane >> 3) & 1, rB = lane & 7;

    /* stage Q (128x64) in stage0 region, pull into registers */
    {
        const bf16* Qg_h = qhi + (size_t)(b * SEQ + m0) * 2304 + h * 64;
        const bf16* Qg_l = qlo + (size_t)(b * SEQ + m0) * 2304 + h * 64;
        int row = tid >> 1, cp = (tid & 1) * 2;
        size_t o = (size_t)row * 2304 + cp * 8;
        cpa16(sb +         a_off(row, cp),     Qg_h + o);
        cpa16(sb +         a_off(row, cp + 1), Qg_h + o + 8);
        cpa16(sb + 16384 + a_off(row, cp),     Qg_l + o);
        cpa16(sb + 16384 + a_off(row, cp + 1), Qg_l + o + 8);
        o += 32;
        cpa16(sb +  8192 + a_off(row, cp),     Qg_h + o);
        cpa16(sb +  8192 + a_off(row, cp + 1), Qg_h + o + 8);
        cpa16(sb + 24576 + a_off(row, cp),     Qg_l + o);
        cpa16(sb + 24576 + a_off(row, cp + 1), Qg_l + o + 8);
        CP_COMMIT(); CP_WAIT(0);
    }
    __syncthreads();
    uint32_t qfh[4][4], qfl[4][4];
    #pragma unroll
    for (int ks = 0; ks < 4; ks++) {
        int off = (ks >> 1) * 8192 + a_off(w * 16 + (jA & 1) * 8 + rA, ((ks & 1) << 1) + (jA >> 1));
        ldsm4(qfh[ks], sb + off);
        ldsm4(qfl[ks], sb + 16384 + off);
    }
    __syncthreads();

    const int kr_row = tid >> 2, kc4 = tid & 3;
    const int vr = tid >> 3, vcb = tid & 7;
    /* K/V tile issue for tile kt into stage s */
    auto issue_kv = [&](int kt, int s) {
        uint32_t base = sb + s * 32768;
        const bf16* Kg_h = qhi + (size_t)(b * SEQ + kt * 64 + kr_row) * 2304 + 768 + h * 64;
        const bf16* Kg_l = qlo + (size_t)(b * SEQ + kt * 64 + kr_row) * 2304 + 768 + h * 64;
        cpa16(base +     0 + a_off(kr_row, kc4), Kg_h + kc4 * 8);
        cpa16(base +  4096 + a_off(kr_row, kc4), Kg_h + 32 + kc4 * 8);
        cpa16(base +  8192 + a_off(kr_row, kc4), Kg_l + kc4 * 8);
        cpa16(base + 12288 + a_off(kr_row, kc4), Kg_l + 32 + kc4 * 8);
        const bf16* Vg_h = qhi + (size_t)(b * SEQ + kt * 64 + vr) * 2304 + 1536 + h * 64 + vcb * 8;
        const bf16* Vg_l = qlo + (size_t)(b * SEQ + kt * 64 + vr) * 2304 + 1536 + h * 64 + vcb * 8;
        cpa16(base + 16384 + bt_off<64>(vr, vcb), Vg_h);
        cpa16(base + 20480 + bt_off<64>(vr, vcb), Vg_h + 32 * 2304);
        cpa16(base + 24576 + bt_off<64>(vr, vcb), Vg_l);
        cpa16(base + 28672 + bt_off<64>(vr, vcb), Vg_l + 32 * 2304);
        CP_COMMIT();
    };

    float oacc[8][4] = {};
    float m_a = -1e30f, m_b = -1e30f, l_a = 0.f, l_b = 0.f;
    const int* mrow_a = mask + (size_t)b * SEQ * SEQ + (size_t)(m0 + w * 16 + (lane >> 2)) * SEQ;
    const int* mrow_b = mrow_a + 8 * SEQ;

    issue_kv(0, 0);
    for (int kt = 0; kt < SEQ / 64; kt++) {
        if (kt + 1 < SEQ / 64) { issue_kv(kt + 1, (kt + 1) & 1); CP_WAIT(1); }
        else                   { CP_WAIT(0); }
        __syncthreads();
        uint32_t st = sb + (kt & 1) * 32768;

        /* S = Q K^T (3-term split) */
        float sacc[8][4] = {};
        #pragma unroll
        for (int ks = 0; ks < 4; ks++) {
            int cbase = (ks >> 1) * 4096;
            int cc = ((ks & 1) << 1) + jB;
            #pragma unroll
            for (int nt = 0; nt < 8; nt++) {
                uint32_t Bh[2], Bl[2];
                int ao = a_off(nt * 8 + rB, cc);
                ldsm2(Bh, st + cbase + ao);
                ldsm2(Bl, st + 8192 + cbase + ao);
                mma_bf16(sacc[nt], qfh[ks], Bh);
                mma_bf16(sacc[nt], qfh[ks], Bl);
                mma_bf16(sacc[nt], qfl[ks], Bh);
            }
        }

        /* mask + scale + online softmax */
        const int* mka = mrow_a + kt * 64 + (lane & 3) * 2;
        const int* mkb = mrow_b + kt * 64 + (lane & 3) * 2;
        float mx_a = -1e30f, mx_b = -1e30f;
        #pragma unroll
        for (int nt = 0; nt < 8; nt++) {
            int2 ma = *(const int2*)(mka + nt * 8);
            int2 mb = *(const int2*)(mkb + nt * 8);
            sacc[nt][0] = ma.x ? sacc[nt][0] * ATTN_SCALE : -10000.f;
            sacc[nt][1] = ma.y ? sacc[nt][1] * ATTN_SCALE : -10000.f;
            sacc[nt][2] = mb.x ? sacc[nt][2] * ATTN_SCALE : -10000.f;
            sacc[nt][3] = mb.y ? sacc[nt][3] * ATTN_SCALE : -10000.f;
            mx_a = fmaxf(mx_a, fmaxf(sacc[nt][0], sacc[nt][1]));
            mx_b = fmaxf(mx_b, fmaxf(sacc[nt][2], sacc[nt][3]));
        }
        mx_a = fmaxf(mx_a, __shfl_xor_sync(0xffffffffu, mx_a, 1));
        mx_a = fmaxf(mx_a, __shfl_xor_sync(0xffffffffu, mx_a, 2));
        mx_b = fmaxf(mx_b, __shfl_xor_sync(0xffffffffu, mx_b, 1));
        mx_b = fmaxf(mx_b, __shfl_xor_sync(0xffffffffu, mx_b, 2));
        float mn_a = fmaxf(m_a, mx_a), mn_b = fmaxf(m_b, mx_b);
        float al_a = __expf(m_a - mn_a), al_b = __expf(m_b - mn_b);
        m_a = mn_a; m_b = mn_b;
        float s_a = 0.f, s_b = 0.f;
        #pragma unroll
        for (int nt = 0; nt < 8; nt++) {
            sacc[nt][0] = __expf(sacc[nt][0] - mn_a);
            sacc[nt][1] = __expf(sacc[nt][1] - mn_a);
            sacc[nt][2] = __expf(sacc[nt][2] - mn_b);
            sacc[nt][3] = __expf(sacc[nt][3] - mn_b);
            s_a += sacc[nt][0] + sacc[nt][1];
            s_b += sacc[nt][2] + sacc[nt][3];
        }
        s_a += __shfl_xor_sync(0xffffffffu, s_a, 1);
        s_a += __shfl_xor_sync(0xffffffffu, s_a, 2);
        s_b += __shfl_xor_sync(0xffffffffu, s_b, 1);
        s_b += __shfl_xor_sync(0xffffffffu, s_b, 2);
        l_a = al_a * l_a + s_a;
        l_b = al_b * l_b + s_b;
        #pragma unroll
        for (int nt = 0; nt < 8; nt++) {
            oacc[nt][0] *= al_a; oacc[nt][1] *= al_a;
            oacc[nt][2] *= al_b; oacc[nt][3] *= al_b;
        }

        /* O += P V (P re-split hi/lo in registers) */
        #pragma unroll
        for (int ks = 0; ks < 4; ks++) {
            uint32_t ph[4], pl[4];
            split2w(sacc[2*ks  ][0], sacc[2*ks  ][1], ph[0], pl[0]);
            split2w(sacc[2*ks  ][2], sacc[2*ks  ][3], ph[1], pl[1]);
            split2w(sacc[2*ks+1][0], sacc[2*ks+1][1], ph[2], pl[2]);
            split2w(sacc[2*ks+1][2], sacc[2*ks+1][3], ph[3], pl[3]);
            int cbase = (ks >> 1) * 4096;
            int krow = (ks & 1) * 16 + jB * 8 + rB;
            #pragma unroll
            for (int nt = 0; nt < 8; nt++) {
                uint32_t Vh[2], Vl[2];
                int vo = bt_off<64>(krow, nt);
                ldsm2t(Vh, st + 16384 + cbase + vo);
                ldsm2t(Vl, st + 24576 + cbase + vo);
                mma_bf16(oacc[nt], ph, Vh);
                mma_bf16(oacc[nt], ph, Vl);
                mma_bf16(oacc[nt], pl, Vh);
            }
        }
        __syncthreads();
    }

    float inv_a = 1.f / l_a, inv_b = 1.f / l_b;
    #pragma unroll
    for (int nt = 0; nt < 8; nt++) {
        int col = h * 64 + nt * 8 + (lane & 3) * 2;
        size_t off = (size_t)(b * SEQ + m0 + w * 16 + (lane >> 2)) * DIM + col;
        store_split2(ohi, olo, off,           oacc[nt][0] * inv_a, oacc[nt][1] * inv_a);
        store_split2(ohi, olo, off + 8 * DIM, oacc[nt][2] * inv_b, oacc[nt][3] * inv_b);
    }
}

/* ================= linear GEMM (cp.async 2-stage) ================= */
template<bool GELU, bool RESID, bool SPLITOUT>
__global__ __launch_bounds__(256) void lin_gemm(
    const bf16* __restrict__ Ahi, const bf16* __restrict__ Alo, int lda,
    const bf16* __restrict__ Whi, const bf16* __restrict__ Wlo, int ldb,
    const float* __restrict__ bias, const float* __restrict__ resid,
    float* __restrict__ outf, bf16* __restrict__ ohi, bf16* __restrict__ olo,
    int ldc, int K)
{
    extern __shared__ __align__(1024) char smx[];
    uint32_t sb = smem_u32(smx);
    const int tid = threadIdx.x, lane = tid & 31, wid = tid >> 5;
    const int wm = wid >> 2, wn = wid & 3;
    const int m0 = blockIdx.y * 128, n0 = blockIdx.x * 128;
    float acc[4][4][4] = {};
    const int nch = K >> 5;

    auto issue = [&](int c, int s) {
        uint32_t base = sb + s * 32768;
        ld_atile_a(base, base + 8192,
                   Ahi + (size_t)m0 * lda + c * 32,
                   Alo + (size_t)m0 * lda + c * 32, lda, tid);
        ld_bttile_a<128>(base + 16384, base + 24576,
                   Whi + (size_t)(c * 32) * ldb + n0,
                   Wlo + (size_t)(c * 32) * ldb + n0, ldb, tid);
        CP_COMMIT();
    };

    issue(0, 0);
    for (int c = 0; c < nch; c++) {
        if (c + 1 < nch) { issue(c + 1, (c + 1) & 1); CP_WAIT(1); }
        else             { CP_WAIT(0); }
        __syncthreads();
        uint32_t st = sb + (c & 1) * 32768;
        mma_chunk<4, true, 128>(st, st + 8192, st + 16384, st + 24576, wm, wn, lane, acc);
        __syncthreads();
    }

    #pragma unroll
    for (int mt = 0; mt < 4; mt++)
        #pragma unroll
        for (int nt = 0; nt < 4; nt++) {
            int n = n0 + wn * 32 + nt * 8 + (lane & 3) * 2;
            float bx = __ldg(bias + n), by = __ldg(bias + n + 1);
            #pragma unroll
            for (int hf = 0; hf < 2; hf++) {
                int m = m0 + wm * 64 + mt * 16 + (lane >> 2) + hf * 8;
                float v0 = acc[mt][nt][hf * 2]     + bx;
                float v1 = acc[mt][nt][hf * 2 + 1] + by;
                if (GELU) {
                    v0 = 0.5f * v0 * (1.f + erff(v0 * 0.7071067811865476f));
                    v1 = 0.5f * v1 * (1.f + erff(v1 * 0.7071067811865476f));
                }
                size_t off = (size_t)m * ldc + n;
                if (SPLITOUT) {
                    store_split2(ohi, olo, off, v0, v1);
                } else {
                    if (RESID) {
                        float2 r = *(const float2*)(resid + off);
                        v0 += r.x; v1 += r.y;
                    }
                    float2 o2; o2.x = v0; o2.y = v1;
                    *(float2*)(outf + off) = o2;
                }
            }
        }
}

/* ================= driver ================= */
extern "C" void kernel_launch(void* const* d_in, const int* in_sizes, int n_in,
                              void* d_out, int out_size)
{
    const float* x      = (const float*)d_in[0];
    const int*   mask   = (const int*)  d_in[1];
    const float* w_qkv  = (const float*)d_in[2];
    const float* b_qkv  = (const float*)d_in[3];
    const float* w_proj = (const float*)d_in[4];
    const float* b_proj = (const float*)d_in[5];
    const float* g1     = (const float*)d_in[6];
    const float* beta1  = (const float*)d_in[7];
    const float* g2     = (const float*)d_in[8];
    const float* beta2  = (const float*)d_in[9];
    const float* w1     = (const float*)d_in[10];
    const float* b1     = (const float*)d_in[11];
    const float* w2     = (const float*)d_in[12];
    const float* b2     = (const float*)d_in[13];
    float* out = (float*)d_out;

    bf16 *hh, *hl, *qh, *ql, *ath, *atl, *h2h, *h2l, *ach, *acl;
    bf16 *wqh, *wql, *wph, *wpl, *w1h, *w1l, *w2h, *w2l;
    float *x1;
    cudaGetSymbolAddress((void**)&hh,  g_h_hi);   cudaGetSymbolAddress((void**)&hl,  g_h_lo);
    cudaGetSymbolAddress((void**)&qh,  g_qkv_hi); cudaGetSymbolAddress((void**)&ql,  g_qkv_lo);
    cudaGetSymbolAddress((void**)&ath, g_at_hi);  cudaGetSymbolAddress((void**)&atl, g_at_lo);
    cudaGetSymbolAddress((void**)&x1,  g_x1);
    cudaGetSymbolAddress((void**)&h2h, g_h2_hi);  cudaGetSymbolAddress((void**)&h2l, g_h2_lo);
    cudaGetSymbolAddress((void**)&ach, g_ac_hi);  cudaGetSymbolAddress((void**)&acl, g_ac_lo);
    cudaGetSymbolAddress((void**)&wqh, g_wqkv_hi); cudaGetSymbolAddress((void**)&wql, g_wqkv_lo);
    cudaGetSymbolAddress((void**)&wph, g_wpr_hi);  cudaGetSymbolAddress((void**)&wpl, g_wpr_lo);
    cudaGetSymbolAddress((void**)&w1h, g_w1_hi);   cudaGetSymbolAddress((void**)&w1l, g_w1_lo);
    cudaGetSymbolAddress((void**)&w2h, g_w2_hi);   cudaGetSymbolAddress((void**)&w2l, g_w2_lo);

    cudaFuncSetAttribute(lin_gemm<false,false,true>,  cudaFuncAttributeMaxDynamicSharedMemorySize, 65536);
    cudaFuncSetAttribute(lin_gemm<false,true,false>,  cudaFuncAttributeMaxDynamicSharedMemorySize, 65536);
    cudaFuncSetAttribute(lin_gemm<true,false,true>,   cudaFuncAttributeMaxDynamicSharedMemorySize, 65536);
    cudaFuncSetAttribute(flash_attn,                  cudaFuncAttributeMaxDynamicSharedMemorySize, 65536);

    wsplit<<<1728, 256>>>(w_qkv,  wqh, wql, 768 * 2304);
    wsplit<<<576,  256>>>(w_proj, wph, wpl, 768 * 768);
    wsplit<<<2304, 256>>>(w1,     w1h, w1l, 768 * 3072);
    wsplit<<<2304, 256>>>(w2,     w2h, w2l, 3072 * 768);

    ln_split<<<NT, 256>>>(x, g1, beta1, hh, hl);
    lin_gemm<false, false, true><<<dim3(18, 64), 256, 65536>>>(
        hh, hl, DIM, wqh, wql, 3 * DIM, b_qkv, nullptr,
        nullptr, qh, ql, 3 * DIM, DIM);
    flash_attn<<<dim3(16, NBH), 256, 65536>>>(qh, ql, mask, ath, atl);
    lin_gemm<false, true, false><<<dim3(6, 64), 256, 65536>>>(
        ath, atl, DIM, wph, wpl, DIM, b_proj, x,
        x1, nullptr, nullptr, DIM, DIM);
    ln_split<<<NT, 256>>>(x1, g2, beta2, h2h, h2l);
    lin_gemm<true, false, true><<<dim3(24, 64), 256, 65536>>>(
        h2h, h2l, DIM, w1h, w1l, HID, b1, nullptr,
        nullptr, ach, acl, HID, DIM);
    lin_gemm<false, true, false><<<dim3(6, 64), 256, 65536>>>(
        ach, acl, HID, w2h, w2l, DIM, b2, x1,
        out, nullptr, nullptr, DIM, HID);
}

// round 9
// speedup vs baseline: 3.0285x; 1.0916x over previous
#include <cuda_runtime.h>
#include <cuda_bf16.h>
#include <math.h>
#include <cstdint>

#define DIM   768
#define NH    12
#define HD    64
#define HID   3072
#define BATCH 4
#define SEQ   2048
#define NT    (BATCH*SEQ)
#define NBH   (BATCH*NH)
#define ATTN_SCALE 0.125f

typedef __nv_bfloat16 bf16;

/* ---------------- scratch planes (device globals) ---------------- */
__device__ unsigned short g_h_hi [(size_t)NT * DIM],      g_h_lo [(size_t)NT * DIM];
__device__ unsigned short g_qkv_hi[(size_t)NT * 3 * DIM], g_qkv_lo[(size_t)NT * 3 * DIM];
__device__ unsigned short g_at_hi[(size_t)NT * DIM],      g_at_lo[(size_t)NT * DIM];
__device__ float          g_x1   [(size_t)NT * DIM];
__device__ unsigned short g_h2_hi[(size_t)NT * DIM],      g_h2_lo[(size_t)NT * DIM];
__device__ unsigned short g_ac_hi[(size_t)NT * HID],      g_ac_lo[(size_t)NT * HID];
__device__ unsigned short g_wqkv_hi[768*2304], g_wqkv_lo[768*2304];
__device__ unsigned short g_wpr_hi [768*768],  g_wpr_lo [768*768];
__device__ unsigned short g_w1_hi  [768*3072], g_w1_lo  [768*3072];
__device__ unsigned short g_w2_hi  [3072*768], g_w2_lo  [3072*768];

/* ---------------- primitives ---------------- */
__device__ __forceinline__ uint32_t smem_u32(const void* p) {
    uint32_t a;
    asm("{ .reg .u64 t; cvta.to.shared.u64 t, %1; cvt.u32.u64 %0, t; }" : "=r"(a) : "l"(p));
    return a;
}
__device__ __forceinline__ void ldsm4(uint32_t* r, uint32_t a) {
    asm volatile("ldmatrix.sync.aligned.m8n8.x4.shared.b16 {%0,%1,%2,%3}, [%4];"
                 : "=r"(r[0]),"=r"(r[1]),"=r"(r[2]),"=r"(r[3]) : "r"(a));
}
__device__ __forceinline__ void ldsm2(uint32_t* r, uint32_t a) {
    asm volatile("ldmatrix.sync.aligned.m8n8.x2.shared.b16 {%0,%1}, [%2];"
                 : "=r"(r[0]),"=r"(r[1]) : "r"(a));
}
__device__ __forceinline__ void ldsm2t(uint32_t* r, uint32_t a) {
    asm volatile("ldmatrix.sync.aligned.m8n8.x2.trans.shared.b16 {%0,%1}, [%2];"
                 : "=r"(r[0]),"=r"(r[1]) : "r"(a));
}
__device__ __forceinline__ void mma_bf16(float* d, const uint32_t* a, const uint32_t* b) {
    asm volatile("mma.sync.aligned.m16n8k16.row.col.f32.bf16.bf16.f32 "
                 "{%0,%1,%2,%3}, {%4,%5,%6,%7}, {%8,%9}, {%0,%1,%2,%3};"
                 : "+f"(d[0]),"+f"(d[1]),"+f"(d[2]),"+f"(d[3])
                 : "r"(a[0]),"r"(a[1]),"r"(a[2]),"r"(a[3]),"r"(b[0]),"r"(b[1]));
}
__device__ __forceinline__ void cpa16(uint32_t dst, const void* src) {
    asm volatile("cp.async.cg.shared.global [%0], [%1], 16;" :: "r"(dst), "l"(src));
}
#define CP_COMMIT() asm volatile("cp.async.commit_group;" ::: "memory")
#define CP_WAIT(n)  asm volatile("cp.async.wait_group %0;" :: "n"(n) : "memory")

/* smem layouts (validated R6/R7):
   A-style tile [rows][32] bf16, 64B rows, swizzle c ^ ((r>>1)&3)
   B-trans tile [32][NTILE] bf16, swizzle c ^ (k&7) */
__device__ __forceinline__ int a_off(int r, int c) { return r * 64 + ((c ^ ((r >> 1) & 3)) << 4); }
template<int NTILE>
__device__ __forceinline__ int bt_off(int k, int c) { return k * (NTILE * 2) + ((c ^ (k & 7)) << 4); }

/* async global -> smem tile loaders (hi+lo planes) */
__device__ __forceinline__ void ld_atile_a(uint32_t dh, uint32_t dl,
    const bf16* gh, const bf16* gl, int stride, int tid)
{
    int row = tid >> 1, cp = (tid & 1) * 2;
    size_t o = (size_t)row * stride + cp * 8;
    cpa16(dh + a_off(row, cp),     gh + o);
    cpa16(dh + a_off(row, cp + 1), gh + o + 8);
    cpa16(dl + a_off(row, cp),     gl + o);
    cpa16(dl + a_off(row, cp + 1), gl + o + 8);
}
template<int NTILE>
__device__ __forceinline__ void ld_bttile_a(uint32_t dh, uint32_t dl,
    const bf16* gh, const bf16* gl, int ldb, int tid)
{
    int k = tid >> 3, cb = tid & 7;
    size_t o = (size_t)k * ldb + cb * 8;
    cpa16(dh + bt_off<NTILE>(k, cb), gh + o);
    cpa16(dl + bt_off<NTILE>(k, cb), gl + o);
    if (NTILE == 128) {
        cpa16(dh + bt_off<NTILE>(k, cb + 8), gh + o + 64);
        cpa16(dl + bt_off<NTILE>(k, cb + 8), gl + o + 64);
    }
}

/* one BK=32 chunk of split-mma: acc += Ah*Bh + Ah*Bl + Al*Bh */
template<int MT, bool BTRANS, int NTILE>
__device__ __forceinline__ void mma_chunk(
    uint32_t sAh, uint32_t sAl, uint32_t sBh, uint32_t sBl,
    int wm, int wn, int lane, float acc[][4][4])
{
    const int jA = lane >> 3, rA = lane & 7;
    const int jB = (lane >> 3) & 1, rB = lane & 7;
    #pragma unroll
    for (int ks = 0; ks < 32; ks += 16) {
        uint32_t Ah[MT][4], Al[MT][4], Bh[4][2], Bl[4][2];
        #pragma unroll
        for (int mt = 0; mt < MT; mt++) {
            int row = wm * MT * 16 + mt * 16 + (jA & 1) * 8 + rA;
            int cc  = (ks >> 3) + (jA >> 1);
            ldsm4(Ah[mt], sAh + a_off(row, cc));
            ldsm4(Al[mt], sAl + a_off(row, cc));
        }
        #pragma unroll
        for (int nt = 0; nt < 4; nt++) {
            if (BTRANS) {
                int krow = ks + jB * 8 + rB;
                int cc   = (wn * 32 + nt * 8) >> 3;
                ldsm2t(Bh[nt], sBh + bt_off<NTILE>(krow, cc));
                ldsm2t(Bl[nt], sBl + bt_off<NTILE>(krow, cc));
            } else {
                int nrow = wn * 32 + nt * 8 + rB;
                int cc   = (ks >> 3) + jB;
                ldsm2(Bh[nt], sBh + a_off(nrow, cc));
                ldsm2(Bl[nt], sBl + a_off(nrow, cc));
            }
        }
        #pragma unroll
        for (int mt = 0; mt < MT; mt++)
            #pragma unroll
            for (int nt = 0; nt < 4; nt++) {
                mma_bf16(acc[mt][nt], Ah[mt], Bh[nt]);
                mma_bf16(acc[mt][nt], Ah[mt], Bl[nt]);
                mma_bf16(acc[mt][nt], Al[mt], Bh[nt]);
            }
    }
}

__device__ __forceinline__ void split2w(float a, float b, uint32_t& hi, uint32_t& lo)
{
    bf16 h0 = __float2bfloat16(a), h1 = __float2bfloat16(b);
    bf16 l0 = __float2bfloat16(a - __bfloat162float(h0));
    bf16 l1 = __float2bfloat16(b - __bfloat162float(h1));
    hi = (uint32_t)__bfloat16_as_ushort(h0) | ((uint32_t)__bfloat16_as_ushort(h1) << 16);
    lo = (uint32_t)__bfloat16_as_ushort(l0) | ((uint32_t)__bfloat16_as_ushort(l1) << 16);
}
__device__ __forceinline__ void store_split2(bf16* hi, bf16* lo, size_t off,
                                             float v0, float v1)
{
    uint32_t H, L;
    split2w(v0, v1, H, L);
    *(uint32_t*)(hi + off) = H;
    *(uint32_t*)(lo + off) = L;
}

/* ================= layernorm -> split planes ================= */
__global__ __launch_bounds__(256) void ln_split(
    const float* __restrict__ x, const float* __restrict__ gamma,
    const float* __restrict__ beta, bf16* __restrict__ ohi, bf16* __restrict__ olo)
{
    int row = blockIdx.x;
    const float* xr = x + (size_t)row * DIM;
    float s = 0.f, s2 = 0.f;
    for (int i = threadIdx.x; i < DIM; i += 256) { float v = xr[i]; s += v; s2 += v * v; }
    __shared__ float sh[64];
    #pragma unroll
    for (int o = 16; o > 0; o >>= 1) {
        s  += __shfl_xor_sync(0xffffffffu, s,  o);
        s2 += __shfl_xor_sync(0xffffffffu, s2, o);
    }
    int warp = threadIdx.x >> 5, lane = threadIdx.x & 31;
    if (lane == 0) { sh[warp] = s; sh[warp + 32] = s2; }
    __syncthreads();
    if (threadIdx.x < 32) {
        s  = (threadIdx.x < 8) ? sh[threadIdx.x]      : 0.f;
        s2 = (threadIdx.x < 8) ? sh[threadIdx.x + 32] : 0.f;
        #pragma unroll
        for (int o = 4; o > 0; o >>= 1) {
            s  += __shfl_xor_sync(0xffffffffu, s,  o);
            s2 += __shfl_xor_sync(0xffffffffu, s2, o);
        }
        if (lane == 0) { sh[0] = s; sh[1] = s2; }
    }
    __syncthreads();
    float mu  = sh[0] * (1.f / DIM);
    float inv = rsqrtf(sh[1] * (1.f / DIM) - mu * mu + 1e-6f);
    for (int i = threadIdx.x; i < DIM; i += 256) {
        float v = (xr[i] - mu) * inv * gamma[i] + beta[i];
        bf16 h = __float2bfloat16(v);
        ohi[(size_t)row * DIM + i] = h;
        olo[(size_t)row * DIM + i] = __float2bfloat16(v - __bfloat162float(h));
    }
}

/* ================= weight split ================= */
__global__ __launch_bounds__(256) void wsplit(
    const float* __restrict__ src, bf16* __restrict__ hi, bf16* __restrict__ lo, int n)
{
    int i = (blockIdx.x * 256 + threadIdx.x) * 4;
    if (i >= n) return;
    float4 v = *(const float4*)(src + i);
    store_split2(hi, lo, i,     v.x, v.y);
    store_split2(hi, lo, i + 2, v.z, v.w);
}

/* ================= fused flash attention (cp.async 3-stage) ================= */
__global__ __launch_bounds__(256) void flash_attn(
    const bf16* __restrict__ qhi, const bf16* __restrict__ qlo,
    const int* __restrict__ mask,
    bf16* __restrict__ ohi, bf16* __restrict__ olo)
{
    extern __shared__ __align__(1024) char smx[];
    uint32_t sb = smem_u32(smx);
    const int tid = threadIdx.x, lane = tid & 31, w = tid >> 5;
    const int z = blockIdx.y, b = z / NH, h = z % NH;
    const int m0 = blockIdx.x * 128;
    const int jA = lane >> 3, rA = lane & 7;
    const int jB = (lane >> 3) & 1, rB = lane & 7;

    /* stage Q (128x64) in first 32KB, pull into registers */
    {
        const bf16* Qg_h = qhi + (size_t)(b * SEQ + m0) * 2304 + h * 64;
        const bf16* Qg_l = qlo + (size_t)(b * SEQ + m0) * 2304 + h * 64;
        int row = tid >> 1, cp = (tid & 1) * 2;
        size_t o = (size_t)row * 2304 + cp * 8;
        cpa16(sb +         a_off(row, cp),     Qg_h + o);
        cpa16(sb +         a_off(row, cp + 1), Qg_h + o + 8);
        cpa16(sb + 16384 + a_off(row, cp),     Qg_l + o);
        cpa16(sb + 16384 + a_off(row, cp + 1), Qg_l + o + 8);
        o += 32;
        cpa16(sb +  8192 + a_off(row, cp),     Qg_h + o);
        cpa16(sb +  8192 + a_off(row, cp + 1), Qg_h + o + 8);
        cpa16(sb + 24576 + a_off(row, cp),     Qg_l + o);
        cpa16(sb + 24576 + a_off(row, cp + 1), Qg_l + o + 8);
        CP_COMMIT(); CP_WAIT(0);
    }
    __syncthreads();
    uint32_t qfh[4][4], qfl[4][4];
    #pragma unroll
    for (int ks = 0; ks < 4; ks++) {
        int off = (ks >> 1) * 8192 + a_off(w * 16 + (jA & 1) * 8 + rA, ((ks & 1) << 1) + (jA >> 1));
        ldsm4(qfh[ks], sb + off);
        ldsm4(qfl[ks], sb + 16384 + off);
    }
    __syncthreads();

    const int kr_row = tid >> 2, kc4 = tid & 3;
    const int vr = tid >> 3, vcb = tid & 7;
    auto issue_kv = [&](int kt, int s) {
        uint32_t base = sb + s * 32768;
        const bf16* Kg_h = qhi + (size_t)(b * SEQ + kt * 64 + kr_row) * 2304 + 768 + h * 64;
        const bf16* Kg_l = qlo + (size_t)(b * SEQ + kt * 64 + kr_row) * 2304 + 768 + h * 64;
        cpa16(base +     0 + a_off(kr_row, kc4), Kg_h + kc4 * 8);
        cpa16(base +  4096 + a_off(kr_row, kc4), Kg_h + 32 + kc4 * 8);
        cpa16(base +  8192 + a_off(kr_row, kc4), Kg_l + kc4 * 8);
        cpa16(base + 12288 + a_off(kr_row, kc4), Kg_l + 32 + kc4 * 8);
        const bf16* Vg_h = qhi + (size_t)(b * SEQ + kt * 64 + vr) * 2304 + 1536 + h * 64 + vcb * 8;
        const bf16* Vg_l = qlo + (size_t)(b * SEQ + kt * 64 + vr) * 2304 + 1536 + h * 64 + vcb * 8;
        cpa16(base + 16384 + bt_off<64>(vr, vcb), Vg_h);
        cpa16(base + 20480 + bt_off<64>(vr, vcb), Vg_h + 32 * 2304);
        cpa16(base + 24576 + bt_off<64>(vr, vcb), Vg_l);
        cpa16(base + 28672 + bt_off<64>(vr, vcb), Vg_l + 32 * 2304);
        CP_COMMIT();
    };

    float oacc[8][4] = {};
    float m_a = -1e30f, m_b = -1e30f, l_a = 0.f, l_b = 0.f;
    const int* mrow_a = mask + (size_t)b * SEQ * SEQ + (size_t)(m0 + w * 16 + (lane >> 2)) * SEQ;
    const int* mrow_b = mrow_a + 8 * SEQ;
    const int nkt = SEQ / 64;

    issue_kv(0, 0);
    issue_kv(1, 1);
    for (int kt = 0; kt < nkt; kt++) {
        if (kt + 1 < nkt) { CP_WAIT(1); } else { CP_WAIT(0); }
        __syncthreads();
        if (kt + 2 < nkt) issue_kv(kt + 2, (kt + 2) % 3);
        uint32_t st = sb + (kt % 3) * 32768;

        /* S = Q K^T (3-term split) */
        float sacc[8][4] = {};
        #pragma unroll
        for (int ks = 0; ks < 4; ks++) {
            int cbase = (ks >> 1) * 4096;
            int cc = ((ks & 1) << 1) + jB;
            #pragma unroll
            for (int nt = 0; nt < 8; nt++) {
                uint32_t Bh[2], Bl[2];
                int ao = a_off(nt * 8 + rB, cc);
                ldsm2(Bh, st + cbase + ao);
                ldsm2(Bl, st + 8192 + cbase + ao);
                mma_bf16(sacc[nt], qfh[ks], Bh);
                mma_bf16(sacc[nt], qfh[ks], Bl);
                mma_bf16(sacc[nt], qfl[ks], Bh);
            }
        }

        /* mask + scale + online softmax */
        const int* mka = mrow_a + kt * 64 + (lane & 3) * 2;
        const int* mkb = mrow_b + kt * 64 + (lane & 3) * 2;
        float mx_a = -1e30f, mx_b = -1e30f;
        #pragma unroll
        for (int nt = 0; nt < 8; nt++) {
            int2 ma = *(const int2*)(mka + nt * 8);
            int2 mb = *(const int2*)(mkb + nt * 8);
            sacc[nt][0] = ma.x ? sacc[nt][0] * ATTN_SCALE : -10000.f;
            sacc[nt][1] = ma.y ? sacc[nt][1] * ATTN_SCALE : -10000.f;
            sacc[nt][2] = mb.x ? sacc[nt][2] * ATTN_SCALE : -10000.f;
            sacc[nt][3] = mb.y ? sacc[nt][3] * ATTN_SCALE : -10000.f;
            mx_a = fmaxf(mx_a, fmaxf(sacc[nt][0], sacc[nt][1]));
            mx_b = fmaxf(mx_b, fmaxf(sacc[nt][2], sacc[nt][3]));
        }
        mx_a = fmaxf(mx_a, __shfl_xor_sync(0xffffffffu, mx_a, 1));
        mx_a = fmaxf(mx_a, __shfl_xor_sync(0xffffffffu, mx_a, 2));
        mx_b = fmaxf(mx_b, __shfl_xor_sync(0xffffffffu, mx_b, 1));
        mx_b = fmaxf(mx_b, __shfl_xor_sync(0xffffffffu, mx_b, 2));
        float mn_a = fmaxf(m_a, mx_a), mn_b = fmaxf(m_b, mx_b);
        float al_a = __expf(m_a - mn_a), al_b = __expf(m_b - mn_b);
        m_a = mn_a; m_b = mn_b;
        float s_a = 0.f, s_b = 0.f;
        #pragma unroll
        for (int nt = 0; nt < 8; nt++) {
            sacc[nt][0] = __expf(sacc[nt][0] - mn_a);
            sacc[nt][1] = __expf(sacc[nt][1] - mn_a);
            sacc[nt][2] = __expf(sacc[nt][2] - mn_b);
            sacc[nt][3] = __expf(sacc[nt][3] - mn_b);
            s_a += sacc[nt][0] + sacc[nt][1];
            s_b += sacc[nt][2] + sacc[nt][3];
        }
        s_a += __shfl_xor_sync(0xffffffffu, s_a, 1);
        s_a += __shfl_xor_sync(0xffffffffu, s_a, 2);
        s_b += __shfl_xor_sync(0xffffffffu, s_b, 1);
        s_b += __shfl_xor_sync(0xffffffffu, s_b, 2);
        l_a = al_a * l_a + s_a;
        l_b = al_b * l_b + s_b;
        #pragma unroll
        for (int nt = 0; nt < 8; nt++) {
            oacc[nt][0] *= al_a; oacc[nt][1] *= al_a;
            oacc[nt][2] *= al_b; oacc[nt][3] *= al_b;
        }

        /* O += P V (P re-split hi/lo in registers) */
        #pragma unroll
        for (int ks = 0; ks < 4; ks++) {
            uint32_t ph[4], pl[4];
            split2w(sacc[2*ks  ][0], sacc[2*ks  ][1], ph[0], pl[0]);
            split2w(sacc[2*ks  ][2], sacc[2*ks  ][3], ph[1], pl[1]);
            split2w(sacc[2*ks+1][0], sacc[2*ks+1][1], ph[2], pl[2]);
            split2w(sacc[2*ks+1][2], sacc[2*ks+1][3], ph[3], pl[3]);
            int cbase = (ks >> 1) * 4096;
            int krow = (ks & 1) * 16 + jB * 8 + rB;
            #pragma unroll
            for (int nt = 0; nt < 8; nt++) {
                uint32_t Vh[2], Vl[2];
                int vo = bt_off<64>(krow, nt);
                ldsm2t(Vh, st + 16384 + cbase + vo);
                ldsm2t(Vl, st + 24576 + cbase + vo);
                mma_bf16(oacc[nt], ph, Vh);
                mma_bf16(oacc[nt], ph, Vl);
                mma_bf16(oacc[nt], pl, Vh);
            }
        }
    }

    float inv_a = 1.f / l_a, inv_b = 1.f / l_b;
    #pragma unroll
    for (int nt = 0; nt < 8; nt++) {
        int col = h * 64 + nt * 8 + (lane & 3) * 2;
        size_t off = (size_t)(b * SEQ + m0 + w * 16 + (lane >> 2)) * DIM + col;
        store_split2(ohi, olo, off,           oacc[nt][0] * inv_a, oacc[nt][1] * inv_a);
        store_split2(ohi, olo, off + 8 * DIM, oacc[nt][2] * inv_b, oacc[nt][3] * inv_b);
    }
}

/* ================= linear GEMM (cp.async 3-stage, 2 CTA/SM) ================= */
template<bool GELU, bool RESID, bool SPLITOUT>
__global__ __launch_bounds__(256, 2) void lin_gemm(
    const bf16* __restrict__ Ahi, const bf16* __restrict__ Alo, int lda,
    const bf16* __restrict__ Whi, const bf16* __restrict__ Wlo, int ldb,
    const float* __restrict__ bias, const float* __restrict__ resid,
    float* __restrict__ outf, bf16* __restrict__ ohi, bf16* __restrict__ olo,
    int ldc, int K)
{
    extern __shared__ __align__(1024) char smx[];
    uint32_t sb = smem_u32(smx);
    const int tid = threadIdx.x, lane = tid & 31, wid = tid >> 5;
    const int wm = wid >> 2, wn = wid & 3;
    const int m0 = blockIdx.y * 128, n0 = blockIdx.x * 128;
    float acc[4][4][4] = {};
    const int nch = K >> 5;

    auto issue = [&](int c, int s) {
        uint32_t base = sb + s * 32768;
        ld_atile_a(base, base + 8192,
                   Ahi + (size_t)m0 * lda + c * 32,
                   Alo + (size_t)m0 * lda + c * 32, lda, tid);
        ld_bttile_a<128>(base + 16384, base + 24576,
                   Whi + (size_t)(c * 32) * ldb + n0,
                   Wlo + (size_t)(c * 32) * ldb + n0, ldb, tid);
        CP_COMMIT();
    };

    issue(0, 0);
    issue(1, 1);
    for (int c = 0; c < nch; c++) {
        if (c + 1 < nch) { CP_WAIT(1); } else { CP_WAIT(0); }
        __syncthreads();
        if (c + 2 < nch) issue(c + 2, (c + 2) % 3);
        uint32_t st = sb + (c % 3) * 32768;
        mma_chunk<4, true, 128>(st, st + 8192, st + 16384, st + 24576, wm, wn, lane, acc);
    }

    #pragma unroll
    for (int mt = 0; mt < 4; mt++)
        #pragma unroll
        for (int nt = 0; nt < 4; nt++) {
            int n = n0 + wn * 32 + nt * 8 + (lane & 3) * 2;
            float bx = __ldg(bias + n), by = __ldg(bias + n + 1);
            #pragma unroll
            for (int hf = 0; hf < 2; hf++) {
                int m = m0 + wm * 64 + mt * 16 + (lane >> 2) + hf * 8;
                float v0 = acc[mt][nt][hf * 2]     + bx;
                float v1 = acc[mt][nt][hf * 2 + 1] + by;
                if (GELU) {
                    v0 = 0.5f * v0 * (1.f + erff(v0 * 0.7071067811865476f));
                    v1 = 0.5f * v1 * (1.f + erff(v1 * 0.7071067811865476f));
                }
                size_t off = (size_t)m * ldc + n;
                if (SPLITOUT) {
                    store_split2(ohi, olo, off, v0, v1);
                } else {
                    if (RESID) {
                        float2 r = *(const float2*)(resid + off);
                        v0 += r.x; v1 += r.y;
                    }
                    float2 o2; o2.x = v0; o2.y = v1;
                    *(float2*)(outf + off) = o2;
                }
            }
        }
}

/* ================= driver ================= */
extern "C" void kernel_launch(void* const* d_in, const int* in_sizes, int n_in,
                              void* d_out, int out_size)
{
    const float* x      = (const float*)d_in[0];
    const int*   mask   = (const int*)  d_in[1];
    const float* w_qkv  = (const float*)d_in[2];
    const float* b_qkv  = (const float*)d_in[3];
    const float* w_proj = (const float*)d_in[4];
    const float* b_proj = (const float*)d_in[5];
    const float* g1     = (const float*)d_in[6];
    const float* beta1  = (const float*)d_in[7];
    const float* g2     = (const float*)d_in[8];
    const float* beta2  = (const float*)d_in[9];
    const float* w1     = (const float*)d_in[10];
    const float* b1     = (const float*)d_in[11];
    const float* w2     = (const float*)d_in[12];
    const float* b2     = (const float*)d_in[13];
    float* out = (float*)d_out;

    bf16 *hh, *hl, *qh, *ql, *ath, *atl, *h2h, *h2l, *ach, *acl;
    bf16 *wqh, *wql, *wph, *wpl, *w1h, *w1l, *w2h, *w2l;
    float *x1;
    cudaGetSymbolAddress((void**)&hh,  g_h_hi);   cudaGetSymbolAddress((void**)&hl,  g_h_lo);
    cudaGetSymbolAddress((void**)&qh,  g_qkv_hi); cudaGetSymbolAddress((void**)&ql,  g_qkv_lo);
    cudaGetSymbolAddress((void**)&ath, g_at_hi);  cudaGetSymbolAddress((void**)&atl, g_at_lo);
    cudaGetSymbolAddress((void**)&x1,  g_x1);
    cudaGetSymbolAddress((void**)&h2h, g_h2_hi);  cudaGetSymbolAddress((void**)&h2l, g_h2_lo);
    cudaGetSymbolAddress((void**)&ach, g_ac_hi);  cudaGetSymbolAddress((void**)&acl, g_ac_lo);
    cudaGetSymbolAddress((void**)&wqh, g_wqkv_hi); cudaGetSymbolAddress((void**)&wql, g_wqkv_lo);
    cudaGetSymbolAddress((void**)&wph, g_wpr_hi);  cudaGetSymbolAddress((void**)&wpl, g_wpr_lo);
    cudaGetSymbolAddress((void**)&w1h, g_w1_hi);   cudaGetSymbolAddress((void**)&w1l, g_w1_lo);
    cudaGetSymbolAddress((void**)&w2h, g_w2_hi);   cudaGetSymbolAddress((void**)&w2l, g_w2_lo);

    cudaFuncSetAttribute(lin_gemm<false,false,true>,  cudaFuncAttributeMaxDynamicSharedMemorySize, 98304);
    cudaFuncSetAttribute(lin_gemm<false,true,false>,  cudaFuncAttributeMaxDynamicSharedMemorySize, 98304);
    cudaFuncSetAttribute(lin_gemm<true,false,true>,   cudaFuncAttributeMaxDynamicSharedMemorySize, 98304);
    cudaFuncSetAttribute(flash_attn,                  cudaFuncAttributeMaxDynamicSharedMemorySize, 98304);

    wsplit<<<1728, 256>>>(w_qkv,  wqh, wql, 768 * 2304);
    wsplit<<<576,  256>>>(w_proj, wph, wpl, 768 * 768);
    wsplit<<<2304, 256>>>(w1,     w1h, w1l, 768 * 3072);
    wsplit<<<2304, 256>>>(w2,     w2h, w2l, 3072 * 768);

    ln_split<<<NT, 256>>>(x, g1, beta1, hh, hl);
    lin_gemm<false, false, true><<<dim3(18, 64), 256, 98304>>>(
        hh, hl, DIM, wqh, wql, 3 * DIM, b_qkv, nullptr,
        nullptr, qh, ql, 3 * DIM, DIM);
    flash_attn<<<dim3(16, NBH), 256, 98304>>>(qh, ql, mask, ath, atl);
    lin_gemm<false, true, false><<<dim3(6, 64), 256, 98304>>>(
        ath, atl, DIM, wph, wpl, DIM, b_proj, x,
        x1, nullptr, nullptr, DIM, DIM);
    ln_split<<<NT, 256>>>(x1, g2, beta2, h2h, h2l);
    lin_gemm<true, false, true><<<dim3(24, 64), 256, 98304>>>(
        h2h, h2l, DIM, w1h, w1l, HID, b1, nullptr,
        nullptr, ach, acl, HID, DIM);
    lin_gemm<false, true, false><<<dim3(6, 64), 256, 98304>>>(
        ach, acl, HID, w2h, w2l, DIM, b2, x1,
        out, nullptr, nullptr, DIM, HID);
}

// round 10
// speedup vs baseline: 3.0354x; 1.0023x over previous
#include <cuda_runtime.h>
#include <cuda_bf16.h>
#include <math.h>
#include <cstdint>

#define DIM   768
#define NH    12
#define HD    64
#define HID   3072
#define BATCH 4
#define SEQ   2048
#define NT    (BATCH*SEQ)
#define NBH   (BATCH*NH)
#define ATTN_SCALE 0.125f

typedef __nv_bfloat16 bf16;

/* ---------------- scratch planes (device globals) ---------------- */
__device__ unsigned short g_h_hi [(size_t)NT * DIM],      g_h_lo [(size_t)NT * DIM];
__device__ unsigned short g_qkv_hi[(size_t)NT * 3 * DIM], g_qkv_lo[(size_t)NT * 3 * DIM];
__device__ unsigned short g_at_hi[(size_t)NT * DIM],      g_at_lo[(size_t)NT * DIM];
__device__ float          g_x1   [(size_t)NT * DIM];
__device__ unsigned short g_h2_hi[(size_t)NT * DIM],      g_h2_lo[(size_t)NT * DIM];
__device__ unsigned short g_ac_hi[(size_t)NT * HID],      g_ac_lo[(size_t)NT * HID];
__device__ unsigned short g_wqkv_hi[768*2304], g_wqkv_lo[768*2304];
__device__ unsigned short g_wpr_hi [768*768],  g_wpr_lo [768*768];
__device__ unsigned short g_w1_hi  [768*3072], g_w1_lo  [768*3072];
__device__ unsigned short g_w2_hi  [3072*768], g_w2_lo  [3072*768];

/* ---------------- primitives ---------------- */
__device__ __forceinline__ uint32_t smem_u32(const void* p) {
    uint32_t a;
    asm("{ .reg .u64 t; cvta.to.shared.u64 t, %1; cvt.u32.u64 %0, t; }" : "=r"(a) : "l"(p));
    return a;
}
__device__ __forceinline__ void ldsm4(uint32_t* r, uint32_t a) {
    asm volatile("ldmatrix.sync.aligned.m8n8.x4.shared.b16 {%0,%1,%2,%3}, [%4];"
                 : "=r"(r[0]),"=r"(r[1]),"=r"(r[2]),"=r"(r[3]) : "r"(a));
}
__device__ __forceinline__ void ldsm2(uint32_t* r, uint32_t a) {
    asm volatile("ldmatrix.sync.aligned.m8n8.x2.shared.b16 {%0,%1}, [%2];"
                 : "=r"(r[0]),"=r"(r[1]) : "r"(a));
}
__device__ __forceinline__ void ldsm2t(uint32_t* r, uint32_t a) {
    asm volatile("ldmatrix.sync.aligned.m8n8.x2.trans.shared.b16 {%0,%1}, [%2];"
                 : "=r"(r[0]),"=r"(r[1]) : "r"(a));
}
__device__ __forceinline__ void mma_bf16(float* d, const uint32_t* a, const uint32_t* b) {
    asm volatile("mma.sync.aligned.m16n8k16.row.col.f32.bf16.bf16.f32 "
                 "{%0,%1,%2,%3}, {%4,%5,%6,%7}, {%8,%9}, {%0,%1,%2,%3};"
                 : "+f"(d[0]),"+f"(d[1]),"+f"(d[2]),"+f"(d[3])
                 : "r"(a[0]),"r"(a[1]),"r"(a[2]),"r"(a[3]),"r"(b[0]),"r"(b[1]));
}
__device__ __forceinline__ void cpa16(uint32_t dst, const void* src) {
    asm volatile("cp.async.cg.shared.global [%0], [%1], 16;" :: "r"(dst), "l"(src));
}
#define CP_COMMIT() asm volatile("cp.async.commit_group;" ::: "memory")
#define CP_WAIT(n)  asm volatile("cp.async.wait_group %0;" :: "n"(n) : "memory")

/* smem layouts (validated R6/R7):
   A-style tile [rows][32] bf16, 64B rows, swizzle c ^ ((r>>1)&3)
   B-trans tile [32][NTILE] bf16, swizzle c ^ (k&7) */
__device__ __forceinline__ int a_off(int r, int c) { return r * 64 + ((c ^ ((r >> 1) & 3)) << 4); }
template<int NTILE>
__device__ __forceinline__ int bt_off(int k, int c) { return k * (NTILE * 2) + ((c ^ (k & 7)) << 4); }

/* async global -> smem tile loaders (hi+lo planes) */
__device__ __forceinline__ void ld_atile_a(uint32_t dh, uint32_t dl,
    const bf16* gh, const bf16* gl, int stride, int tid)
{
    int row = tid >> 1, cp = (tid & 1) * 2;
    size_t o = (size_t)row * stride + cp * 8;
    cpa16(dh + a_off(row, cp),     gh + o);
    cpa16(dh + a_off(row, cp + 1), gh + o + 8);
    cpa16(dl + a_off(row, cp),     gl + o);
    cpa16(dl + a_off(row, cp + 1), gl + o + 8);
}
template<int NTILE>
__device__ __forceinline__ void ld_bttile_a(uint32_t dh, uint32_t dl,
    const bf16* gh, const bf16* gl, int ldb, int tid)
{
    int k = tid >> 3, cb = tid & 7;
    size_t o = (size_t)k * ldb + cb * 8;
    cpa16(dh + bt_off<NTILE>(k, cb), gh + o);
    cpa16(dl + bt_off<NTILE>(k, cb), gl + o);
    if (NTILE == 128) {
        cpa16(dh + bt_off<NTILE>(k, cb + 8), gh + o + 64);
        cpa16(dl + bt_off<NTILE>(k, cb + 8), gl + o + 64);
    }
}

/* one BK=32 chunk of split-mma, TERM-OUTER ordering:
   all independent (mt,nt) MMAs of one term issued before the next term
   touches the same accumulators (16-deep independence window). */
template<int MT, bool BTRANS, int NTILE>
__device__ __forceinline__ void mma_chunk(
    uint32_t sAh, uint32_t sAl, uint32_t sBh, uint32_t sBl,
    int wm, int wn, int lane, float acc[][4][4])
{
    const int jA = lane >> 3, rA = lane & 7;
    const int jB = (lane >> 3) & 1, rB = lane & 7;
    #pragma unroll
    for (int ks = 0; ks < 32; ks += 16) {
        uint32_t Ah[MT][4], Al[MT][4], Bh[4][2], Bl[4][2];
        #pragma unroll
        for (int mt = 0; mt < MT; mt++) {
            int row = wm * MT * 16 + mt * 16 + (jA & 1) * 8 + rA;
            int cc  = (ks >> 3) + (jA >> 1);
            ldsm4(Ah[mt], sAh + a_off(row, cc));
            ldsm4(Al[mt], sAl + a_off(row, cc));
        }
        #pragma unroll
        for (int nt = 0; nt < 4; nt++) {
            if (BTRANS) {
                int krow = ks + jB * 8 + rB;
                int cc   = (wn * 32 + nt * 8) >> 3;
                ldsm2t(Bh[nt], sBh + bt_off<NTILE>(krow, cc));
                ldsm2t(Bl[nt], sBl + bt_off<NTILE>(krow, cc));
            } else {
                int nrow = wn * 32 + nt * 8 + rB;
                int cc   = (ks >> 3) + jB;
                ldsm2(Bh[nt], sBh + a_off(nrow, cc));
                ldsm2(Bl[nt], sBl + a_off(nrow, cc));
            }
        }
        #pragma unroll
        for (int mt = 0; mt < MT; mt++)
            #pragma unroll
            for (int nt = 0; nt < 4; nt++)
                mma_bf16(acc[mt][nt], Ah[mt], Bh[nt]);
        #pragma unroll
        for (int mt = 0; mt < MT; mt++)
            #pragma unroll
            for (int nt = 0; nt < 4; nt++)
                mma_bf16(acc[mt][nt], Ah[mt], Bl[nt]);
        #pragma unroll
        for (int mt = 0; mt < MT; mt++)
            #pragma unroll
            for (int nt = 0; nt < 4; nt++)
                mma_bf16(acc[mt][nt], Al[mt], Bh[nt]);
    }
}

__device__ __forceinline__ void split2w(float a, float b, uint32_t& hi, uint32_t& lo)
{
    bf16 h0 = __float2bfloat16(a), h1 = __float2bfloat16(b);
    bf16 l0 = __float2bfloat16(a - __bfloat162float(h0));
    bf16 l1 = __float2bfloat16(b - __bfloat162float(h1));
    hi = (uint32_t)__bfloat16_as_ushort(h0) | ((uint32_t)__bfloat16_as_ushort(h1) << 16);
    lo = (uint32_t)__bfloat16_as_ushort(l0) | ((uint32_t)__bfloat16_as_ushort(l1) << 16);
}
__device__ __forceinline__ void store_split2(bf16* hi, bf16* lo, size_t off,
                                             float v0, float v1)
{
    uint32_t H, L;
    split2w(v0, v1, H, L);
    *(uint32_t*)(hi + off) = H;
    *(uint32_t*)(lo + off) = L;
}

/* ================= layernorm -> split planes ================= */
__global__ __launch_bounds__(256) void ln_split(
    const float* __restrict__ x, const float* __restrict__ gamma,
    const float* __restrict__ beta, bf16* __restrict__ ohi, bf16* __restrict__ olo)
{
    int row = blockIdx.x;
    const float* xr = x + (size_t)row * DIM;
    float s = 0.f, s2 = 0.f;
    for (int i = threadIdx.x; i < DIM; i += 256) { float v = xr[i]; s += v; s2 += v * v; }
    __shared__ float sh[64];
    #pragma unroll
    for (int o = 16; o > 0; o >>= 1) {
        s  += __shfl_xor_sync(0xffffffffu, s,  o);
        s2 += __shfl_xor_sync(0xffffffffu, s2, o);
    }
    int warp = threadIdx.x >> 5, lane = threadIdx.x & 31;
    if (lane == 0) { sh[warp] = s; sh[warp + 32] = s2; }
    __syncthreads();
    if (threadIdx.x < 32) {
        s  = (threadIdx.x < 8) ? sh[threadIdx.x]      : 0.f;
        s2 = (threadIdx.x < 8) ? sh[threadIdx.x + 32] : 0.f;
        #pragma unroll
        for (int o = 4; o > 0; o >>= 1) {
            s  += __shfl_xor_sync(0xffffffffu, s,  o);
            s2 += __shfl_xor_sync(0xffffffffu, s2, o);
        }
        if (lane == 0) { sh[0] = s; sh[1] = s2; }
    }
    __syncthreads();
    float mu  = sh[0] * (1.f / DIM);
    float inv = rsqrtf(sh[1] * (1.f / DIM) - mu * mu + 1e-6f);
    for (int i = threadIdx.x; i < DIM; i += 256) {
        float v = (xr[i] - mu) * inv * gamma[i] + beta[i];
        bf16 h = __float2bfloat16(v);
        ohi[(size_t)row * DIM + i] = h;
        olo[(size_t)row * DIM + i] = __float2bfloat16(v - __bfloat162float(h));
    }
}

/* ================= weight split ================= */
__global__ __launch_bounds__(256) void wsplit(
    const float* __restrict__ src, bf16* __restrict__ hi, bf16* __restrict__ lo, int n)
{
    int i = (blockIdx.x * 256 + threadIdx.x) * 4;
    if (i >= n) return;
    float4 v = *(const float4*)(src + i);
    store_split2(hi, lo, i,     v.x, v.y);
    store_split2(hi, lo, i + 2, v.z, v.w);
}

/* ================= fused flash attention (cp.async 3-stage) ================= */
__global__ __launch_bounds__(256) void flash_attn(
    const bf16* __restrict__ qhi, const bf16* __restrict__ qlo,
    const int* __restrict__ mask,
    bf16* __restrict__ ohi, bf16* __restrict__ olo)
{
    extern __shared__ __align__(1024) char smx[];
    uint32_t sb = smem_u32(smx);
    const int tid = threadIdx.x, lane = tid & 31, w = tid >> 5;
    const int z = blockIdx.y, b = z / NH, h = z % NH;
    const int m0 = blockIdx.x * 128;
    const int jA = lane >> 3, rA = lane & 7;
    const int jB = (lane >> 3) & 1, rB = lane & 7;

    /* stage Q (128x64) in first 32KB, pull into registers */
    {
        const bf16* Qg_h = qhi + (size_t)(b * SEQ + m0) * 2304 + h * 64;
        const bf16* Qg_l = qlo + (size_t)(b * SEQ + m0) * 2304 + h * 64;
        int row = tid >> 1, cp = (tid & 1) * 2;
        size_t o = (size_t)row * 2304 + cp * 8;
        cpa16(sb +         a_off(row, cp),     Qg_h + o);
        cpa16(sb +         a_off(row, cp + 1), Qg_h + o + 8);
        cpa16(sb + 16384 + a_off(row, cp),     Qg_l + o);
        cpa16(sb + 16384 + a_off(row, cp + 1), Qg_l + o + 8);
        o += 32;
        cpa16(sb +  8192 + a_off(row, cp),     Qg_h + o);
        cpa16(sb +  8192 + a_off(row, cp + 1), Qg_h + o + 8);
        cpa16(sb + 24576 + a_off(row, cp),     Qg_l + o);
        cpa16(sb + 24576 + a_off(row, cp + 1), Qg_l + o + 8);
        CP_COMMIT(); CP_WAIT(0);
    }
    __syncthreads();
    uint32_t qfh[4][4], qfl[4][4];
    #pragma unroll
    for (int ks = 0; ks < 4; ks++) {
        int off = (ks >> 1) * 8192 + a_off(w * 16 + (jA & 1) * 8 + rA, ((ks & 1) << 1) + (jA >> 1));
        ldsm4(qfh[ks], sb + off);
        ldsm4(qfl[ks], sb + 16384 + off);
    }
    __syncthreads();

    const int kr_row = tid >> 2, kc4 = tid & 3;
    const int vr = tid >> 3, vcb = tid & 7;
    auto issue_kv = [&](int kt, int s) {
        uint32_t base = sb + s * 32768;
        const bf16* Kg_h = qhi + (size_t)(b * SEQ + kt * 64 + kr_row) * 2304 + 768 + h * 64;
        const bf16* Kg_l = qlo + (size_t)(b * SEQ + kt * 64 + kr_row) * 2304 + 768 + h * 64;
        cpa16(base +     0 + a_off(kr_row, kc4), Kg_h + kc4 * 8);
        cpa16(base +  4096 + a_off(kr_row, kc4), Kg_h + 32 + kc4 * 8);
        cpa16(base +  8192 + a_off(kr_row, kc4), Kg_l + kc4 * 8);
        cpa16(base + 12288 + a_off(kr_row, kc4), Kg_l + 32 + kc4 * 8);
        const bf16* Vg_h = qhi + (size_t)(b * SEQ + kt * 64 + vr) * 2304 + 1536 + h * 64 + vcb * 8;
        const bf16* Vg_l = qlo + (size_t)(b * SEQ + kt * 64 + vr) * 2304 + 1536 + h * 64 + vcb * 8;
        cpa16(base + 16384 + bt_off<64>(vr, vcb), Vg_h);
        cpa16(base + 20480 + bt_off<64>(vr, vcb), Vg_h + 32 * 2304);
        cpa16(base + 24576 + bt_off<64>(vr, vcb), Vg_l);
        cpa16(base + 28672 + bt_off<64>(vr, vcb), Vg_l + 32 * 2304);
        CP_COMMIT();
    };

    float oacc[8][4] = {};
    float m_a = -1e30f, m_b = -1e30f, l_a = 0.f, l_b = 0.f;
    const int* mrow_a = mask + (size_t)b * SEQ * SEQ + (size_t)(m0 + w * 16 + (lane >> 2)) * SEQ;
    const int* mrow_b = mrow_a + 8 * SEQ;
    const int nkt = SEQ / 64;

    issue_kv(0, 0);
    issue_kv(1, 1);
    for (int kt = 0; kt < nkt; kt++) {
        if (kt + 1 < nkt) { CP_WAIT(1); } else { CP_WAIT(0); }
        __syncthreads();
        if (kt + 2 < nkt) issue_kv(kt + 2, (kt + 2) % 3);
        uint32_t st = sb + (kt % 3) * 32768;

        /* S = Q K^T: per ks preload all 8 B pairs, then term-outer sweeps */
        float sacc[8][4] = {};
        #pragma unroll
        for (int ks = 0; ks < 4; ks++) {
            int cbase = (ks >> 1) * 4096;
            int cc = ((ks & 1) << 1) + jB;
            uint32_t Bh[8][2], Bl[8][2];
            #pragma unroll
            for (int nt = 0; nt < 8; nt++) {
                int ao = a_off(nt * 8 + rB, cc);
                ldsm2(Bh[nt], st + cbase + ao);
                ldsm2(Bl[nt], st + 8192 + cbase + ao);
            }
            #pragma unroll
            for (int nt = 0; nt < 8; nt++) mma_bf16(sacc[nt], qfh[ks], Bh[nt]);
            #pragma unroll
            for (int nt = 0; nt < 8; nt++) mma_bf16(sacc[nt], qfh[ks], Bl[nt]);
            #pragma unroll
            for (int nt = 0; nt < 8; nt++) mma_bf16(sacc[nt], qfl[ks], Bh[nt]);
        }

        /* mask + scale + online softmax */
        const int* mka = mrow_a + kt * 64 + (lane & 3) * 2;
        const int* mkb = mrow_b + kt * 64 + (lane & 3) * 2;
        float mx_a = -1e30f, mx_b = -1e30f;
        #pragma unroll
        for (int nt = 0; nt < 8; nt++) {
            int2 ma = *(const int2*)(mka + nt * 8);
            int2 mb = *(const int2*)(mkb + nt * 8);
            sacc[nt][0] = ma.x ? sacc[nt][0] * ATTN_SCALE : -10000.f;
            sacc[nt][1] = ma.y ? sacc[nt][1] * ATTN_SCALE : -10000.f;
            sacc[nt][2] = mb.x ? sacc[nt][2] * ATTN_SCALE : -10000.f;
            sacc[nt][3] = mb.y ? sacc[nt][3] * ATTN_SCALE : -10000.f;
            mx_a = fmaxf(mx_a, fmaxf(sacc[nt][0], sacc[nt][1]));
            mx_b = fmaxf(mx_b, fmaxf(sacc[nt][2], sacc[nt][3]));
        }
        mx_a = fmaxf(mx_a, __shfl_xor_sync(0xffffffffu, mx_a, 1));
        mx_a = fmaxf(mx_a, __shfl_xor_sync(0xffffffffu, mx_a, 2));
        mx_b = fmaxf(mx_b, __shfl_xor_sync(0xffffffffu, mx_b, 1));
        mx_b = fmaxf(mx_b, __shfl_xor_sync(0xffffffffu, mx_b, 2));
        float mn_a = fmaxf(m_a, mx_a), mn_b = fmaxf(m_b, mx_b);
        float al_a = __expf(m_a - mn_a), al_b = __expf(m_b - mn_b);
        m_a = mn_a; m_b = mn_b;
        float s_a = 0.f, s_b = 0.f;
        #pragma unroll
        for (int nt = 0; nt < 8; nt++) {
            sacc[nt][0] = __expf(sacc[nt][0] - mn_a);
            sacc[nt][1] = __expf(sacc[nt][1] - mn_a);
            sacc[nt][2] = __expf(sacc[nt][2] - mn_b);
            sacc[nt][3] = __expf(sacc[nt][3] - mn_b);
            s_a += sacc[nt][0] + sacc[nt][1];
            s_b += sacc[nt][2] + sacc[nt][3];
        }
        s_a += __shfl_xor_sync(0xffffffffu, s_a, 1);
        s_a += __shfl_xor_sync(0xffffffffu, s_a, 2);
        s_b += __shfl_xor_sync(0xffffffffu, s_b, 1);
        s_b += __shfl_xor_sync(0xffffffffu, s_b, 2);
        l_a = al_a * l_a + s_a;
        l_b = al_b * l_b + s_b;
        #pragma unroll
        for (int nt = 0; nt < 8; nt++) {
            oacc[nt][0] *= al_a; oacc[nt][1] *= al_a;
            oacc[nt][2] *= al_b; oacc[nt][3] *= al_b;
        }

        /* O += P V: per ks preload all 8 V pairs, then term-outer sweeps */
        #pragma unroll
        for (int ks = 0; ks < 4; ks++) {
            uint32_t ph[4], pl[4];
            split2w(sacc[2*ks  ][0], sacc[2*ks  ][1], ph[0], pl[0]);
            split2w(sacc[2*ks  ][2], sacc[2*ks  ][3], ph[1], pl[1]);
            split2w(sacc[2*ks+1][0], sacc[2*ks+1][1], ph[2], pl[2]);
            split2w(sacc[2*ks+1][2], sacc[2*ks+1][3], ph[3], pl[3]);
            int cbase = (ks >> 1) * 4096;
            int krow = (ks & 1) * 16 + jB * 8 + rB;
            uint32_t Vh[8][2], Vl[8][2];
            #pragma unroll
            for (int nt = 0; nt < 8; nt++) {
                int vo = bt_off<64>(krow, nt);
                ldsm2t(Vh[nt], st + 16384 + cbase + vo);
                ldsm2t(Vl[nt], st + 24576 + cbase + vo);
            }
            #pragma unroll
            for (int nt = 0; nt < 8; nt++) mma_bf16(oacc[nt], ph, Vh[nt]);
            #pragma unroll
            for (int nt = 0; nt < 8; nt++) mma_bf16(oacc[nt], ph, Vl[nt]);
            #pragma unroll
            for (int nt = 0; nt < 8; nt++) mma_bf16(oacc[nt], pl, Vh[nt]);
        }
    }

    float inv_a = 1.f / l_a, inv_b = 1.f / l_b;
    #pragma unroll
    for (int nt = 0; nt < 8; nt++) {
        int col = h * 64 + nt * 8 + (lane & 3) * 2;
        size_t off = (size_t)(b * SEQ + m0 + w * 16 + (lane >> 2)) * DIM + col;
        store_split2(ohi, olo, off,           oacc[nt][0] * inv_a, oacc[nt][1] * inv_a);
        store_split2(ohi, olo, off + 8 * DIM, oacc[nt][2] * inv_b, oacc[nt][3] * inv_b);
    }
}

/* ================= linear GEMM (cp.async 3-stage, 2 CTA/SM) ================= */
template<bool GELU, bool RESID, bool SPLITOUT>
__global__ __launch_bounds__(256, 2) void lin_gemm(
    const bf16* __restrict__ Ahi, const bf16* __restrict__ Alo, int lda,
    const bf16* __restrict__ Whi, const bf16* __restrict__ Wlo, int ldb,
    const float* __restrict__ bias, const float* __restrict__ resid,
    float* __restrict__ outf, bf16* __restrict__ ohi, bf16* __restrict__ olo,
    int ldc, int K)
{
    extern __shared__ __align__(1024) char smx[];
    uint32_t sb = smem_u32(smx);
    const int tid = threadIdx.x, lane = tid & 31, wid = tid >> 5;
    const int wm = wid >> 2, wn = wid & 3;
    const int m0 = blockIdx.y * 128, n0 = blockIdx.x * 128;
    float acc[4][4][4] = {};
    const int nch = K >> 5;

    auto issue = [&](int c, int s) {
        uint32_t base = sb + s * 32768;
        ld_atile_a(base, base + 8192,
                   Ahi + (size_t)m0 * lda + c * 32,
                   Alo + (size_t)m0 * lda + c * 32, lda, tid);
        ld_bttile_a<128>(base + 16384, base + 24576,
                   Whi + (size_t)(c * 32) * ldb + n0,
                   Wlo + (size_t)(c * 32) * ldb + n0, ldb, tid);
        CP_COMMIT();
    };

    issue(0, 0);
    issue(1, 1);
    for (int c = 0; c < nch; c++) {
        if (c + 1 < nch) { CP_WAIT(1); } else { CP_WAIT(0); }
        __syncthreads();
        if (c + 2 < nch) issue(c + 2, (c + 2) % 3);
        uint32_t st = sb + (c % 3) * 32768;
        mma_chunk<4, true, 128>(st, st + 8192, st + 16384, st + 24576, wm, wn, lane, acc);
    }

    #pragma unroll
    for (int mt = 0; mt < 4; mt++)
        #pragma unroll
        for (int nt = 0; nt < 4; nt++) {
            int n = n0 + wn * 32 + nt * 8 + (lane & 3) * 2;
            float bx = __ldg(bias + n), by = __ldg(bias + n + 1);
            #pragma unroll
            for (int hf = 0; hf < 2; hf++) {
                int m = m0 + wm * 64 + mt * 16 + (lane >> 2) + hf * 8;
                float v0 = acc[mt][nt][hf * 2]     + bx;
                float v1 = acc[mt][nt][hf * 2 + 1] + by;
                if (GELU) {
                    v0 = 0.5f * v0 * (1.f + erff(v0 * 0.7071067811865476f));
                    v1 = 0.5f * v1 * (1.f + erff(v1 * 0.7071067811865476f));
                }
                size_t off = (size_t)m * ldc + n;
                if (SPLITOUT) {
                    store_split2(ohi, olo, off, v0, v1);
                } else {
                    if (RESID) {
                        float2 r = *(const float2*)(resid + off);
                        v0 += r.x; v1 += r.y;
                    }
                    float2 o2; o2.x = v0; o2.y = v1;
                    *(float2*)(outf + off) = o2;
                }
            }
        }
}

/* ================= driver ================= */
extern "C" void kernel_launch(void* const* d_in, const int* in_sizes, int n_in,
                              void* d_out, int out_size)
{
    const float* x      = (const float*)d_in[0];
    const int*   mask   = (const int*)  d_in[1];
    const float* w_qkv  = (const float*)d_in[2];
    const float* b_qkv  = (const float*)d_in[3];
    const float* w_proj = (const float*)d_in[4];
    const float* b_proj = (const float*)d_in[5];
    const float* g1     = (const float*)d_in[6];
    const float* beta1  = (const float*)d_in[7];
    const float* g2     = (const float*)d_in[8];
    const float* beta2  = (const float*)d_in[9];
    const float* w1     = (const float*)d_in[10];
    const float* b1     = (const float*)d_in[11];
    const float* w2     = (const float*)d_in[12];
    const float* b2     = (const float*)d_in[13];
    float* out = (float*)d_out;

    bf16 *hh, *hl, *qh, *ql, *ath, *atl, *h2h, *h2l, *ach, *acl;
    bf16 *wqh, *wql, *wph, *wpl, *w1h, *w1l, *w2h, *w2l;
    float *x1;
    cudaGetSymbolAddress((void**)&hh,  g_h_hi);   cudaGetSymbolAddress((void**)&hl,  g_h_lo);
    cudaGetSymbolAddress((void**)&qh,  g_qkv_hi); cudaGetSymbolAddress((void**)&ql,  g_qkv_lo);
    cudaGetSymbolAddress((void**)&ath, g_at_hi);  cudaGetSymbolAddress((void**)&atl, g_at_lo);
    cudaGetSymbolAddress((void**)&x1,  g_x1);
    cudaGetSymbolAddress((void**)&h2h, g_h2_hi);  cudaGetSymbolAddress((void**)&h2l, g_h2_lo);
    cudaGetSymbolAddress((void**)&ach, g_ac_hi);  cudaGetSymbolAddress((void**)&acl, g_ac_lo);
    cudaGetSymbolAddress((void**)&wqh, g_wqkv_hi); cudaGetSymbolAddress((void**)&wql, g_wqkv_lo);
    cudaGetSymbolAddress((void**)&wph, g_wpr_hi);  cudaGetSymbolAddress((void**)&wpl, g_wpr_lo);
    cudaGetSymbolAddress((void**)&w1h, g_w1_hi);   cudaGetSymbolAddress((void**)&w1l, g_w1_lo);
    cudaGetSymbolAddress((void**)&w2h, g_w2_hi);   cudaGetSymbolAddress((void**)&w2l, g_w2_lo);

    cudaFuncSetAttribute(lin_gemm<false,false,true>,  cudaFuncAttributeMaxDynamicSharedMemorySize, 98304);
    cudaFuncSetAttribute(lin_gemm<false,true,false>,  cudaFuncAttributeMaxDynamicSharedMemorySize, 98304);
    cudaFuncSetAttribute(lin_gemm<true,false,true>,   cudaFuncAttributeMaxDynamicSharedMemorySize, 98304);
    cudaFuncSetAttribute(flash_attn,                  cudaFuncAttributeMaxDynamicSharedMemorySize, 98304);

    wsplit<<<1728, 256>>>(w_qkv,  wqh, wql, 768 * 2304);
    wsplit<<<576,  256>>>(w_proj, wph, wpl, 768 * 768);
    wsplit<<<2304, 256>>>(w1,     w1h, w1l, 768 * 3072);
    wsplit<<<2304, 256>>>(w2,     w2h, w2l, 3072 * 768);

    ln_split<<<NT, 256>>>(x, g1, beta1, hh, hl);
    lin_gemm<false, false, true><<<dim3(18, 64), 256, 98304>>>(
        hh, hl, DIM, wqh, wql, 3 * DIM, b_qkv, nullptr,
        nullptr, qh, ql, 3 * DIM, DIM);
    flash_attn<<<dim3(16, NBH), 256, 98304>>>(qh, ql, mask, ath, atl);
    lin_gemm<false, true, false><<<dim3(6, 64), 256, 98304>>>(
        ath, atl, DIM, wph, wpl, DIM, b_proj, x,
        x1, nullptr, nullptr, DIM, DIM);
    ln_split<<<NT, 256>>>(x1, g2, beta2, h2h, h2l);
    lin_gemm<true, false, true><<<dim3(24, 64), 256, 98304>>>(
        h2h, h2l, DIM, w1h, w1l, HID, b1, nullptr,
        nullptr, ach, acl, HID, DIM);
    lin_gemm<false, true, false><<<dim3(6, 64), 256, 98304>>>(
        ach, acl, HID, w2h, w2l, DIM, b2, x1,
        out, nullptr, nullptr, DIM, HID);
}